// round 12
// baseline (speedup 1.0000x reference)
#include <cuda_runtime.h>
#include <cuda_bf16.h>
#include <math.h>
#include <stdint.h>

// ---------------- problem dims ----------------
#define T_    1024
#define B_    4
#define E_    512
#define H_    8
#define D_    64
#define DFF_  2048
#define NTOK  4096
#define PLEN  2047
#define KCONV 31

typedef unsigned long long u64;

// ---------------- scratch ----------------
__device__ float g_ff[NTOK * DFF_];
__device__ float g_x1[NTOK * E_];
__device__ float g_x2[NTOK * E_];
__device__ float g_x3[NTOK * E_];
__device__ float g_qkv[NTOK * 3 * E_];
__device__ float g_pproj[PLEN * E_];
__device__ float g_glu[NTOK * E_];
__device__ __nv_bfloat16 g_whi[7339520];
__device__ __nv_bfloat16 g_wlo[7339520];
__device__ __nv_bfloat16 g_ahi[NTOK * DFF_];
__device__ __nv_bfloat16 g_alo[NTOK * DFF_];
__device__ __nv_bfloat16 g_bhi[NTOK * DFF_];
__device__ __nv_bfloat16 g_blo[NTOK * DFF_];

// packed weight offsets (elements)
#define OFF_FFM_W1 0
#define OFF_FFM_W2 1048576
#define OFF_IN_W   2097152
#define OFF_WPOS   2883584
#define OFF_OUT_W  3145728
#define OFF_PW1_W  3407872
#define OFF_PW2_W  3932160
#define OFF_FF_W1  4194304
#define OFF_FF_W2  5242880
#define OFF_POSE   6291456

__device__ __forceinline__ float sigmoidf_(float x) { return 1.f / (1.f + __expf(-x)); }

// ---------------- packed f32x2 helpers ----------------
__device__ __forceinline__ u64 pack2_(float lo, float hi) {
    u64 r; asm("mov.b64 %0, {%1, %2};" : "=l"(r) : "f"(lo), "f"(hi)); return r;
}
__device__ __forceinline__ u64 pdup_(float x) {
    u64 r; asm("mov.b64 %0, {%1, %1};" : "=l"(r) : "f"(x)); return r;
}
__device__ __forceinline__ u64 ffma2_(u64 a, u64 b, u64 c) {
    u64 d; asm("fma.rn.f32x2 %0, %1, %2, %3;" : "=l"(d) : "l"(a), "l"(b), "l"(c)); return d;
}
__device__ __forceinline__ u64 mul2_(u64 a, u64 b) {
    u64 d; asm("mul.rn.f32x2 %0, %1, %2;" : "=l"(d) : "l"(a), "l"(b)); return d;
}
__device__ __forceinline__ float2 unpack2_(u64 v) {
    float2 f; asm("mov.b64 {%0, %1}, %2;" : "=f"(f.x), "=f"(f.y) : "l"(v)); return f;
}
__device__ __forceinline__ uint32_t smem_u32_(const void* p) {
    return (uint32_t)__cvta_generic_to_shared(p);
}
__device__ __forceinline__ void cpasync16_(uint32_t dst, const void* src, int srcbytes) {
    asm volatile("cp.async.ca.shared.global [%0], [%1], 16, %2;"
                 :: "r"(dst), "l"(src), "r"(srcbytes));
}
__device__ __forceinline__ void split2_(float v0, float v1,
                                        __nv_bfloat16* hi, __nv_bfloat16* lo, size_t off) {
    __nv_bfloat16 h0 = __float2bfloat16(v0);
    __nv_bfloat16 h1 = __float2bfloat16(v1);
    __nv_bfloat162 hp; hp.x = h0; hp.y = h1;
    __nv_bfloat162 lp;
    lp.x = __float2bfloat16(v0 - __bfloat162float(h0));
    lp.y = __float2bfloat16(v1 - __bfloat162float(h1));
    *(__nv_bfloat162*)(hi + off) = hp;
    *(__nv_bfloat162*)(lo + off) = lp;
}

// ---------------- multi-segment hi/lo split ----------------
#define NSEG 11
struct SplitArgs {
    const float* src[NSEG];
    __nv_bfloat16* hi[NSEG];
    __nv_bfloat16* lo[NSEG];
    int n[NSEG];
};

__global__ void split_multi_kernel(SplitArgs a)
{
    int seg = blockIdx.y;
    int i = blockIdx.x * 256 + threadIdx.x;
    if (i >= a.n[seg]) return;
    float x = a.src[seg][i];
    __nv_bfloat16 h = __float2bfloat16(x);
    a.hi[seg][i] = h;
    a.lo[seg][i] = __float2bfloat16(x - __bfloat162float(h));
}

// ---------------- bf16 mma.sync NT GEMM: 128x128, fused 3-term, 2 CTAs/SM ----------------
enum { EPI_NONE = 0, EPI_DSWISH = 1, EPI_RES = 2 };
#define SSTRIDE 40
#define TILE_E  (128 * SSTRIDE)
#define STAGE_E (4 * TILE_E)
#define GEMM_SMEM_B (2 * STAGE_E * 2)    // 81920 bytes

template <int EPI, int WC, int WS>
__global__ void __launch_bounds__(256, 2)
gemm_mma_kernel(const __nv_bfloat16* __restrict__ Ahi, const __nv_bfloat16* __restrict__ Alo,
                const __nv_bfloat16* __restrict__ Bhi, const __nv_bfloat16* __restrict__ Blo,
                const float* __restrict__ bias, const float* __restrict__ res,
                float* __restrict__ C,
                __nv_bfloat16* __restrict__ Ohi, __nv_bfloat16* __restrict__ Olo,
                int M, int N, int K)
{
    extern __shared__ __nv_bfloat16 smem_g[];

    const int tid = threadIdx.x;
    const int wid = tid >> 5;
    const int lane = tid & 31;
    const int m0 = blockIdx.y * 128, n0 = blockIdx.x * 128;
    const int nk = K >> 5;

    const int mw = (wid & 1) * 64;
    const int nw = (wid >> 1) * 32;

    float acc[4][4][4];
#pragma unroll
    for (int a = 0; a < 4; a++)
#pragma unroll
        for (int b = 0; b < 4; b++)
#pragma unroll
            for (int c = 0; c < 4; c++) acc[a][b][c] = 0.f;

    const int r0 = tid >> 2,         col0 = (tid & 3) << 3;
    const int r1 = (tid + 256) >> 2, col1 = ((tid + 256) & 3) << 3;
    const uint32_t s_u = smem_u32_(smem_g);
    const uint32_t d0 = (uint32_t)(r0 * SSTRIDE + col0) * 2;
    const uint32_t d1 = (uint32_t)(r1 * SSTRIDE + col1) * 2;
    const int am0 = m0 + r0, am1 = m0 + r1;
    const int asz0 = am0 < M ? 16 : 0;
    const int asz1 = am1 < M ? 16 : 0;
    const size_t arow0 = (size_t)(am0 < M ? am0 : 0) * K;
    const size_t arow1 = (size_t)(am1 < M ? am1 : 0) * K;
    const size_t brow0 = (size_t)(n0 + r0) * K;
    const size_t brow1 = (size_t)(n0 + r1) * K;

    auto issue_loads = [&](int kt) {
        int kk0 = kt << 5;
        uint32_t so = (kt & 1) ? (uint32_t)STAGE_E * 2 : 0u;
        cpasync16_(s_u + so + d0, Ahi + arow0 + kk0 + col0, asz0);
        cpasync16_(s_u + so + d1, Ahi + arow1 + kk0 + col1, asz1);
        cpasync16_(s_u + so + TILE_E * 2 + d0, Alo + arow0 + kk0 + col0, asz0);
        cpasync16_(s_u + so + TILE_E * 2 + d1, Alo + arow1 + kk0 + col1, asz1);
        cpasync16_(s_u + so + 2 * TILE_E * 2 + d0, Bhi + brow0 + kk0 + col0, 16);
        cpasync16_(s_u + so + 2 * TILE_E * 2 + d1, Bhi + brow1 + kk0 + col1, 16);
        cpasync16_(s_u + so + 3 * TILE_E * 2 + d0, Blo + brow0 + kk0 + col0, 16);
        cpasync16_(s_u + so + 3 * TILE_E * 2 + d1, Blo + brow1 + kk0 + col1, 16);
    };

    issue_loads(0);
    asm volatile("cp.async.commit_group;" ::: "memory");

    const int lr8 = lane & 7;
    const int sel = lane >> 3;

#define MMA_(AH, BF)                                                            \
            _Pragma("unroll")                                                   \
            for (int mt = 0; mt < 4; mt++) {                                    \
                _Pragma("unroll")                                               \
                for (int nt = 0; nt < 4; nt++) {                                \
                    uint32_t b0 = BF[nt >> 1][(nt & 1) * 2 + 0];                \
                    uint32_t b1 = BF[nt >> 1][(nt & 1) * 2 + 1];                \
                    asm volatile(                                               \
                        "mma.sync.aligned.m16n8k16.row.col.f32.bf16.bf16.f32 "  \
                        "{%0,%1,%2,%3}, {%4,%5,%6,%7}, {%8,%9}, {%0,%1,%2,%3};" \
                        : "+f"(acc[mt][nt][0]), "+f"(acc[mt][nt][1]),           \
                          "+f"(acc[mt][nt][2]), "+f"(acc[mt][nt][3])            \
                        : "r"(AH[mt][0]), "r"(AH[mt][1]),                       \
                          "r"(AH[mt][2]), "r"(AH[mt][3]),                       \
                          "r"(b0), "r"(b1));                                    \
                }                                                               \
            }

    for (int kt = 0; kt < nk; kt++) {
        if (kt + 1 < nk) issue_loads(kt + 1);
        asm volatile("cp.async.commit_group;" ::: "memory");
        asm volatile("cp.async.wait_group 1;" ::: "memory");
        __syncthreads();

        const uint32_t base = s_u + ((kt & 1) ? (uint32_t)STAGE_E * 2 : 0u);
#pragma unroll
        for (int kk = 0; kk < 2; kk++) {
            uint32_t ahi[4][4];
#pragma unroll
            for (int mt = 0; mt < 4; mt++) {
                int row = mw + mt * 16 + lr8 + (sel & 1) * 8;
                int col = kk * 16 + (sel >> 1) * 8;
                uint32_t addr = base + (uint32_t)(row * SSTRIDE + col) * 2;
                asm volatile("ldmatrix.sync.aligned.m8n8.x4.shared.b16 {%0,%1,%2,%3}, [%4];"
                             : "=r"(ahi[mt][0]), "=r"(ahi[mt][1]), "=r"(ahi[mt][2]), "=r"(ahi[mt][3])
                             : "r"(addr));
            }
            uint32_t bfr[2][4];
#pragma unroll
            for (int np = 0; np < 2; np++) {
                int row = nw + np * 16 + lr8 + (sel >> 1) * 8;
                int col = kk * 16 + (sel & 1) * 8;
                uint32_t addr = base + 2 * TILE_E * 2 + (uint32_t)(row * SSTRIDE + col) * 2;
                asm volatile("ldmatrix.sync.aligned.m8n8.x4.shared.b16 {%0,%1,%2,%3}, [%4];"
                             : "=r"(bfr[np][0]), "=r"(bfr[np][1]), "=r"(bfr[np][2]), "=r"(bfr[np][3])
                             : "r"(addr));
            }
            MMA_(ahi, bfr)

            {
                uint32_t alo[4][4];
#pragma unroll
                for (int mt = 0; mt < 4; mt++) {
                    int row = mw + mt * 16 + lr8 + (sel & 1) * 8;
                    int col = kk * 16 + (sel >> 1) * 8;
                    uint32_t addr = base + TILE_E * 2 + (uint32_t)(row * SSTRIDE + col) * 2;
                    asm volatile("ldmatrix.sync.aligned.m8n8.x4.shared.b16 {%0,%1,%2,%3}, [%4];"
                                 : "=r"(alo[mt][0]), "=r"(alo[mt][1]), "=r"(alo[mt][2]), "=r"(alo[mt][3])
                                 : "r"(addr));
                }
                MMA_(alo, bfr)
            }

#pragma unroll
            for (int np = 0; np < 2; np++) {
                int row = nw + np * 16 + lr8 + (sel >> 1) * 8;
                int col = kk * 16 + (sel & 1) * 8;
                uint32_t addr = base + 3 * TILE_E * 2 + (uint32_t)(row * SSTRIDE + col) * 2;
                asm volatile("ldmatrix.sync.aligned.m8n8.x4.shared.b16 {%0,%1,%2,%3}, [%4];"
                             : "=r"(bfr[np][0]), "=r"(bfr[np][1]), "=r"(bfr[np][2]), "=r"(bfr[np][3])
                             : "r"(addr));
            }
            MMA_(ahi, bfr)
        }
        __syncthreads();
    }
#undef MMA_

    const int g = lane >> 2, t4 = lane & 3;
#pragma unroll
    for (int mt = 0; mt < 4; mt++) {
#pragma unroll
        for (int rr = 0; rr < 2; rr++) {
            int row = m0 + mw + mt * 16 + g + rr * 8;
            if (row >= M) continue;
#pragma unroll
            for (int nt = 0; nt < 4; nt++) {
                int col = n0 + nw + nt * 8 + t4 * 2;
                float v0 = acc[mt][nt][rr * 2 + 0];
                float v1 = acc[mt][nt][rr * 2 + 1];
                if (bias) { v0 += bias[col]; v1 += bias[col + 1]; }
                if (EPI == EPI_DSWISH) {
                    v0 = v0 * sigmoidf_(v0 - 1.f);
                    v1 = v1 * sigmoidf_(v1 - 1.f);
                }
                size_t off = (size_t)row * N + col;
                if (EPI == EPI_RES) {
                    float2 rv = *(const float2*)&res[off];
                    v0 += rv.x; v1 += rv.y;
                }
                if (WC) *(float2*)&C[off] = make_float2(v0, v1);
                if (WS) split2_(v0, v1, Ohi, Olo, off);
            }
        }
    }
}

// ---------------- bf16 mma.sync NT GEMM: 128x64 tile (narrow-N), 2 CTAs/SM ----------------
#define AT_E  (128 * SSTRIDE)
#define BT64_E (64 * SSTRIDE)
#define STAGE64_E (2 * AT_E + 2 * BT64_E)
#define GEMM64_SMEM_B (2 * STAGE64_E * 2)   // 61440 bytes

template <int EPI, int WC, int WS>
__global__ void __launch_bounds__(256, 2)
gemm_mma64_kernel(const __nv_bfloat16* __restrict__ Ahi, const __nv_bfloat16* __restrict__ Alo,
                  const __nv_bfloat16* __restrict__ Bhi, const __nv_bfloat16* __restrict__ Blo,
                  const float* __restrict__ bias, const float* __restrict__ res,
                  float* __restrict__ C,
                  __nv_bfloat16* __restrict__ Ohi, __nv_bfloat16* __restrict__ Olo,
                  int M, int N, int K)
{
    extern __shared__ __nv_bfloat16 smem_g[];

    const int tid = threadIdx.x;
    const int wid = tid >> 5;
    const int lane = tid & 31;
    const int m0 = blockIdx.y * 128, n0 = blockIdx.x * 64;
    const int nk = K >> 5;

    const int mw = (wid & 1) * 64;
    const int nw = (wid >> 1) * 16;

    float acc[4][2][4];
#pragma unroll
    for (int a = 0; a < 4; a++)
#pragma unroll
        for (int b = 0; b < 2; b++)
#pragma unroll
            for (int c = 0; c < 4; c++) acc[a][b][c] = 0.f;

    const uint32_t s_u = smem_u32_(smem_g);
    // A: 512 16B-chunks (2/thread/array); B: 256 chunks (1/thread/array)
    const int r0 = tid >> 2,         col0 = (tid & 3) << 3;
    const int r1 = (tid + 256) >> 2, col1 = ((tid + 256) & 3) << 3;
    const uint32_t d0 = (uint32_t)(r0 * SSTRIDE + col0) * 2;
    const uint32_t d1 = (uint32_t)(r1 * SSTRIDE + col1) * 2;
    const int am0 = m0 + r0, am1 = m0 + r1;
    const int asz0 = am0 < M ? 16 : 0;
    const int asz1 = am1 < M ? 16 : 0;
    const size_t arow0 = (size_t)(am0 < M ? am0 : 0) * K;
    const size_t arow1 = (size_t)(am1 < M ? am1 : 0) * K;
    const size_t brow0 = (size_t)(n0 + r0) * K;   // r0 in 0..63 for B chunks (tid<256 -> r0<64)

    auto issue_loads = [&](int kt) {
        int kk0 = kt << 5;
        uint32_t so = (kt & 1) ? (uint32_t)STAGE64_E * 2 : 0u;
        cpasync16_(s_u + so + d0, Ahi + arow0 + kk0 + col0, asz0);
        cpasync16_(s_u + so + d1, Ahi + arow1 + kk0 + col1, asz1);
        cpasync16_(s_u + so + AT_E * 2 + d0, Alo + arow0 + kk0 + col0, asz0);
        cpasync16_(s_u + so + AT_E * 2 + d1, Alo + arow1 + kk0 + col1, asz1);
        cpasync16_(s_u + so + 2 * AT_E * 2 + d0, Bhi + brow0 + kk0 + col0, 16);
        cpasync16_(s_u + so + 2 * AT_E * 2 + BT64_E * 2 + d0, Blo + brow0 + kk0 + col0, 16);
    };

    issue_loads(0);
    asm volatile("cp.async.commit_group;" ::: "memory");

    const int lr8 = lane & 7;
    const int sel = lane >> 3;

#define MMA64_(AH, BF)                                                          \
            _Pragma("unroll")                                                   \
            for (int mt = 0; mt < 4; mt++) {                                    \
                _Pragma("unroll")                                               \
                for (int nt = 0; nt < 2; nt++) {                                \
                    uint32_t b0 = BF[nt * 2 + 0];                               \
                    uint32_t b1 = BF[nt * 2 + 1];                               \
                    asm volatile(                                               \
                        "mma.sync.aligned.m16n8k16.row.col.f32.bf16.bf16.f32 "  \
                        "{%0,%1,%2,%3}, {%4,%5,%6,%7}, {%8,%9}, {%0,%1,%2,%3};" \
                        : "+f"(acc[mt][nt][0]), "+f"(acc[mt][nt][1]),           \
                          "+f"(acc[mt][nt][2]), "+f"(acc[mt][nt][3])            \
                        : "r"(AH[mt][0]), "r"(AH[mt][1]),                       \
                          "r"(AH[mt][2]), "r"(AH[mt][3]),                       \
                          "r"(b0), "r"(b1));                                    \
                }                                                               \
            }

    for (int kt = 0; kt < nk; kt++) {
        if (kt + 1 < nk) issue_loads(kt + 1);
        asm volatile("cp.async.commit_group;" ::: "memory");
        asm volatile("cp.async.wait_group 1;" ::: "memory");
        __syncthreads();

        const uint32_t base = s_u + ((kt & 1) ? (uint32_t)STAGE64_E * 2 : 0u);
#pragma unroll
        for (int kk = 0; kk < 2; kk++) {
            uint32_t ahi[4][4];
#pragma unroll
            for (int mt = 0; mt < 4; mt++) {
                int row = mw + mt * 16 + lr8 + (sel & 1) * 8;
                int col = kk * 16 + (sel >> 1) * 8;
                uint32_t addr = base + (uint32_t)(row * SSTRIDE + col) * 2;
                asm volatile("ldmatrix.sync.aligned.m8n8.x4.shared.b16 {%0,%1,%2,%3}, [%4];"
                             : "=r"(ahi[mt][0]), "=r"(ahi[mt][1]), "=r"(ahi[mt][2]), "=r"(ahi[mt][3])
                             : "r"(addr));
            }
            uint32_t bfr[4];
            {
                int row = nw + lr8 + (sel >> 1) * 8;
                int col = kk * 16 + (sel & 1) * 8;
                uint32_t addr = base + 2 * AT_E * 2 + (uint32_t)(row * SSTRIDE + col) * 2;
                asm volatile("ldmatrix.sync.aligned.m8n8.x4.shared.b16 {%0,%1,%2,%3}, [%4];"
                             : "=r"(bfr[0]), "=r"(bfr[1]), "=r"(bfr[2]), "=r"(bfr[3])
                             : "r"(addr));
            }
            MMA64_(ahi, bfr)

            {
                uint32_t alo[4][4];
#pragma unroll
                for (int mt = 0; mt < 4; mt++) {
                    int row = mw + mt * 16 + lr8 + (sel & 1) * 8;
                    int col = kk * 16 + (sel >> 1) * 8;
                    uint32_t addr = base + AT_E * 2 + (uint32_t)(row * SSTRIDE + col) * 2;
                    asm volatile("ldmatrix.sync.aligned.m8n8.x4.shared.b16 {%0,%1,%2,%3}, [%4];"
                                 : "=r"(alo[mt][0]), "=r"(alo[mt][1]), "=r"(alo[mt][2]), "=r"(alo[mt][3])
                                 : "r"(addr));
                }
                MMA64_(alo, bfr)
            }

            {
                int row = nw + lr8 + (sel >> 1) * 8;
                int col = kk * 16 + (sel & 1) * 8;
                uint32_t addr = base + 2 * AT_E * 2 + BT64_E * 2 + (uint32_t)(row * SSTRIDE + col) * 2;
                asm volatile("ldmatrix.sync.aligned.m8n8.x4.shared.b16 {%0,%1,%2,%3}, [%4];"
                             : "=r"(bfr[0]), "=r"(bfr[1]), "=r"(bfr[2]), "=r"(bfr[3])
                             : "r"(addr));
            }
            MMA64_(ahi, bfr)
        }
        __syncthreads();
    }
#undef MMA64_

    const int g = lane >> 2, t4 = lane & 3;
#pragma unroll
    for (int mt = 0; mt < 4; mt++) {
#pragma unroll
        for (int rr = 0; rr < 2; rr++) {
            int row = m0 + mw + mt * 16 + g + rr * 8;
            if (row >= M) continue;
#pragma unroll
            for (int nt = 0; nt < 2; nt++) {
                int col = n0 + nw + nt * 8 + t4 * 2;
                float v0 = acc[mt][nt][rr * 2 + 0];
                float v1 = acc[mt][nt][rr * 2 + 1];
                if (bias) { v0 += bias[col]; v1 += bias[col + 1]; }
                if (EPI == EPI_DSWISH) {
                    v0 = v0 * sigmoidf_(v0 - 1.f);
                    v1 = v1 * sigmoidf_(v1 - 1.f);
                }
                size_t off = (size_t)row * N + col;
                if (EPI == EPI_RES) {
                    float2 rv = *(const float2*)&res[off];
                    v0 += rv.x; v1 += rv.y;
                }
                if (WC) *(float2*)&C[off] = make_float2(v0, v1);
                if (WS) split2_(v0, v1, Ohi, Olo, off);
            }
        }
    }
}

// ---------------- fused attention (transposed Qu/Kt, 2 CTAs/SM) ----------------
#define ATTN_SMEM ((64 * 68 + 64 + 64 * 68 + 64 * 128 + 64 * 68 + 64 * 68) * 4)

__global__ void __launch_bounds__(256, 2)
attn_fused_kernel(const float* __restrict__ qkv,
                  const float* __restrict__ pproj,
                  const float* __restrict__ u,
                  const float* __restrict__ v,
                  __nv_bfloat16* __restrict__ chi,
                  __nv_bfloat16* __restrict__ clo)
{
    extern __shared__ float sm[];
    float* Qu  = sm;
    float* duv = Qu + 64 * 68;
    float* Kt  = duv + 64;
    float* Ps  = Kt + 64 * 68;
    float* Vs  = Ps + 64 * 128;
    float* Es  = Vs + 64 * 68;

    const int bh = blockIdx.y;
    const int b = bh >> 3, h = bh & 7;
    const int i0 = blockIdx.x * 64;
    const int tid = threadIdx.x;
    const float scale = 0.125f;

    for (int idx = tid; idx < 64 * 64; idx += 256) {
        int li = idx >> 6, d = idx & 63;
        float q = qkv[(size_t)((i0 + li) * B_ + b) * (3 * E_) + h * 64 + d] * scale;
        Qu[d * 68 + li] = q + u[h * 64 + d];
    }
    if (tid < 64) duv[tid] = v[h * 64 + tid] - u[h * 64 + tid];

    const int tm = (tid >> 4) << 2;
    const int tn = (tid & 15) << 2;
    const int base = 63 - tm + tn;

    float mrow[4], lrow[4];
#pragma unroll
    for (int i = 0; i < 4; i++) { mrow[i] = -1e30f; lrow[i] = 0.f; }
    u64 outacc[4][2];
#pragma unroll
    for (int i = 0; i < 4; i++) { outacc[i][0] = 0ull; outacc[i][1] = 0ull; }

    for (int j0 = 0; j0 < T_; j0 += 64) {
        __syncthreads();
        for (int idx = tid; idx < 64 * 64; idx += 256) {
            int li = idx >> 6, d = idx & 63;
            size_t rb = (size_t)((j0 + li) * B_ + b) * (3 * E_) + h * 64 + d;
            Kt[d * 68 + li] = qkv[rb + E_];
            Vs[li * 68 + d] = qkv[rb + 2 * E_];
        }
        const int m_min = 960 - i0 + j0;
        for (int idx = tid; idx < 64 * 127; idx += 256) {
            int d = idx / 127, mm = idx % 127;
            Ps[d * 128 + mm] = pproj[(size_t)(m_min + mm) * E_ + h * 64 + d];
        }
        __syncthreads();

        u64 acc2[4][2];
#pragma unroll
        for (int i = 0; i < 4; i++) { acc2[i][0] = 0ull; acc2[i][1] = 0ull; }

#pragma unroll 4
        for (int d = 0; d < 64; d++) {
            float duvd = duv[d];
            float4 qu4 = *(const float4*)&Qu[d * 68 + tm];
            float4 kt4 = *(const float4*)&Kt[d * 68 + tn];
            u64 ad[4], cd[4];
            ad[0] = pdup_(qu4.x); cd[0] = pdup_(qu4.x + duvd);
            ad[1] = pdup_(qu4.y); cd[1] = pdup_(qu4.y + duvd);
            ad[2] = pdup_(qu4.z); cd[2] = pdup_(qu4.z + duvd);
            ad[3] = pdup_(qu4.w); cd[3] = pdup_(qu4.w + duvd);
            u64 kb0 = pack2_(kt4.x, kt4.y), kb1 = pack2_(kt4.z, kt4.w);
            float p7[7];
#pragma unroll
            for (int t = 0; t < 7; t++) p7[t] = Ps[d * 128 + base + t - 3];
            u64 pp[6];
#pragma unroll
            for (int t = 0; t < 6; t++) pp[t] = pack2_(p7[t], p7[t + 1]);
#pragma unroll
            for (int ii = 0; ii < 4; ii++) {
                acc2[ii][0] = ffma2_(ad[ii], kb0, acc2[ii][0]);
                acc2[ii][1] = ffma2_(ad[ii], kb1, acc2[ii][1]);
                acc2[ii][0] = ffma2_(cd[ii], pp[3 - ii], acc2[ii][0]);
                acc2[ii][1] = ffma2_(cd[ii], pp[5 - ii], acc2[ii][1]);
            }
        }

#pragma unroll
        for (int ii = 0; ii < 4; ii++) {
            float2 t0 = unpack2_(acc2[ii][0]);
            float2 t1 = unpack2_(acc2[ii][1]);
            float s0 = t0.x, s1 = t0.y, s2 = t1.x, s3 = t1.y;
            float mx = fmaxf(fmaxf(s0, s1), fmaxf(s2, s3));
#pragma unroll
            for (int o = 1; o < 16; o <<= 1)
                mx = fmaxf(mx, __shfl_xor_sync(0xffffffffu, mx, o));
            float mnew = fmaxf(mrow[ii], mx);
            float alpha = __expf(mrow[ii] - mnew);
            mrow[ii] = mnew;
            s0 = __expf(s0 - mnew); s1 = __expf(s1 - mnew);
            s2 = __expf(s2 - mnew); s3 = __expf(s3 - mnew);
            float rs = s0 + s1 + s2 + s3;
#pragma unroll
            for (int o = 1; o < 16; o <<= 1)
                rs += __shfl_xor_sync(0xffffffffu, rs, o);
            lrow[ii] = lrow[ii] * alpha + rs;
            u64 al = pdup_(alpha);
            outacc[ii][0] = mul2_(outacc[ii][0], al);
            outacc[ii][1] = mul2_(outacc[ii][1], al);
            *(float4*)&Es[(tm + ii) * 68 + tn] = make_float4(s0, s1, s2, s3);
        }
        __syncthreads();

#pragma unroll 8
        for (int kk = 0; kk < 64; kk++) {
            ulonglong2 bq = *(const ulonglong2*)&Vs[kk * 68 + tn];
#pragma unroll
            for (int ii = 0; ii < 4; ii++) {
                u64 a = pdup_(Es[(tm + ii) * 68 + kk]);
                outacc[ii][0] = ffma2_(a, bq.x, outacc[ii][0]);
                outacc[ii][1] = ffma2_(a, bq.y, outacc[ii][1]);
            }
        }
    }

#pragma unroll
    for (int ii = 0; ii < 4; ii++) {
        float inv = 1.f / lrow[ii];
        float2 t0 = unpack2_(outacc[ii][0]);
        float2 t1 = unpack2_(outacc[ii][1]);
        size_t off = (size_t)((i0 + tm + ii) * B_ + b) * E_ + h * 64 + tn;
        split2_(t0.x * inv, t0.y * inv, chi, clo, off);
        split2_(t1.x * inv, t1.y * inv, chi, clo, off + 2);
    }
}

// ---------------- GLU ----------------
__global__ void glu_kernel(const float* __restrict__ y, float* __restrict__ out)
{
    int idx = blockIdx.x * 256 + threadIdx.x;
    if (idx >= NTOK * E_) return;
    int r = idx >> 9, c = idx & 511;
    float a = y[(size_t)r * 1024 + c];
    float g = y[(size_t)r * 1024 + 512 + c];
    out[idx] = a * sigmoidf_(g);
}

// ---------------- depthwise conv + DoubleSwish -> split bf16 ----------------
__global__ void dwconv_kernel(const float* __restrict__ x, const float* __restrict__ w,
                              const float* __restrict__ bias,
                              __nv_bfloat16* __restrict__ ohi, __nv_bfloat16* __restrict__ olo)
{
    int idx = blockIdx.x * 256 + threadIdx.x;
    if (idx >= NTOK * E_) return;
    int c = idx & 511;
    int tb = idx >> 9;
    int t = tb >> 2, b = tb & 3;
    float acc = bias[c];
#pragma unroll
    for (int k = 0; k < KCONV; k++) {
        int tt = t + k - 15;
        if (tt >= 0 && tt < T_)
            acc += x[(size_t)(tt * B_ + b) * E_ + c] * w[c * KCONV + k];
    }
    float vv = acc * sigmoidf_(acc - 1.f);
    __nv_bfloat16 h = __float2bfloat16(vv);
    ohi[idx] = h;
    olo[idx] = __float2bfloat16(vv - __bfloat162float(h));
}

// ---------------- BasicNorm ----------------
__global__ void basic_norm_kernel(const float* __restrict__ x, const float* __restrict__ leps,
                                  float* __restrict__ out)
{
    __shared__ float red[8];
    const int tid = threadIdx.x;
    const float* p = x + (size_t)blockIdx.x * E_;
    float v0 = p[tid], v1 = p[tid + 256];
    float ss = v0 * v0 + v1 * v1;
#pragma unroll
    for (int o = 16; o > 0; o >>= 1) ss += __shfl_xor_sync(0xffffffffu, ss, o);
    if ((tid & 31) == 0) red[tid >> 5] = ss;
    __syncthreads();
    float tot = red[0];
#pragma unroll
    for (int i = 1; i < 8; i++) tot += red[i];
    float r = rsqrtf(tot * (1.f / (float)E_) + __expf(leps[0]));
    out[(size_t)blockIdx.x * E_ + tid]       = v0 * r;
    out[(size_t)blockIdx.x * E_ + tid + 256] = v1 * r;
}

// ---------------- launch ----------------
extern "C" void kernel_launch(void* const* d_in, const int* in_sizes, int n_in,
                              void* d_out, int out_size)
{
    const float* src      = (const float*)d_in[0];
    const float* pos_emb  = (const float*)d_in[1];
    const float* in_w     = (const float*)d_in[2];
    const float* in_b     = (const float*)d_in[3];
    const float* out_w    = (const float*)d_in[4];
    const float* out_b    = (const float*)d_in[5];
    const float* wpos     = (const float*)d_in[6];
    const float* u        = (const float*)d_in[7];
    const float* v        = (const float*)d_in[8];
    const float* ffm_w1   = (const float*)d_in[9];
    const float* ffm_b1   = (const float*)d_in[10];
    const float* ffm_w2   = (const float*)d_in[11];
    const float* ffm_b2   = (const float*)d_in[12];
    const float* ff_w1    = (const float*)d_in[13];
    const float* ff_b1    = (const float*)d_in[14];
    const float* ff_w2    = (const float*)d_in[15];
    const float* ff_b2    = (const float*)d_in[16];
    const float* pw1_w    = (const float*)d_in[17];
    const float* pw1_b    = (const float*)d_in[18];
    const float* dw_w     = (const float*)d_in[19];
    const float* dw_b     = (const float*)d_in[20];
    const float* pw2_w    = (const float*)d_in[21];
    const float* pw2_b    = (const float*)d_in[22];
    const float* leps     = (const float*)d_in[23];

    float *ff, *x1, *x2, *x3, *qkv, *pp, *glu;
    __nv_bfloat16 *whi, *wlo, *ahi, *alo, *bhi, *blo;
    cudaGetSymbolAddress((void**)&ff,  g_ff);
    cudaGetSymbolAddress((void**)&x1,  g_x1);
    cudaGetSymbolAddress((void**)&x2,  g_x2);
    cudaGetSymbolAddress((void**)&x3,  g_x3);
    cudaGetSymbolAddress((void**)&qkv, g_qkv);
    cudaGetSymbolAddress((void**)&pp,  g_pproj);
    cudaGetSymbolAddress((void**)&glu, g_glu);
    cudaGetSymbolAddress((void**)&whi, g_whi);
    cudaGetSymbolAddress((void**)&wlo, g_wlo);
    cudaGetSymbolAddress((void**)&ahi, g_ahi);
    cudaGetSymbolAddress((void**)&alo, g_alo);
    cudaGetSymbolAddress((void**)&bhi, g_bhi);
    cudaGetSymbolAddress((void**)&blo, g_blo);

    cudaFuncSetAttribute(attn_fused_kernel, cudaFuncAttributeMaxDynamicSharedMemorySize,
                         ATTN_SMEM);
#define SET_GSMEM(EPI, WC, WS) \
    cudaFuncSetAttribute((gemm_mma_kernel<EPI, WC, WS>), \
                         cudaFuncAttributeMaxDynamicSharedMemorySize, GEMM_SMEM_B)
    SET_GSMEM(EPI_DSWISH, 0, 1);
    SET_GSMEM(EPI_RES, 1, 1);
    SET_GSMEM(EPI_NONE, 1, 0);
#undef SET_GSMEM
#define SET_G64SMEM(EPI, WC, WS) \
    cudaFuncSetAttribute((gemm_mma64_kernel<EPI, WC, WS>), \
                         cudaFuncAttributeMaxDynamicSharedMemorySize, GEMM64_SMEM_B)
    SET_G64SMEM(EPI_RES, 1, 1);
    SET_G64SMEM(EPI_RES, 1, 0);
    SET_G64SMEM(EPI_NONE, 1, 0);
#undef SET_G64SMEM

    // launch 0: all splits in one kernel
    SplitArgs sa;
    sa.src[0] = ffm_w1;  sa.hi[0] = whi + OFF_FFM_W1; sa.lo[0] = wlo + OFF_FFM_W1; sa.n[0] = DFF_ * E_;
    sa.src[1] = ffm_w2;  sa.hi[1] = whi + OFF_FFM_W2; sa.lo[1] = wlo + OFF_FFM_W2; sa.n[1] = E_ * DFF_;
    sa.src[2] = in_w;    sa.hi[2] = whi + OFF_IN_W;   sa.lo[2] = wlo + OFF_IN_W;   sa.n[2] = 3 * E_ * E_;
    sa.src[3] = wpos;    sa.hi[3] = whi + OFF_WPOS;   sa.lo[3] = wlo + OFF_WPOS;   sa.n[3] = E_ * E_;
    sa.src[4] = out_w;   sa.hi[4] = whi + OFF_OUT_W;  sa.lo[4] = wlo + OFF_OUT_W;  sa.n[4] = E_ * E_;
    sa.src[5] = pw1_w;   sa.hi[5] = whi + OFF_PW1_W;  sa.lo[5] = wlo + OFF_PW1_W;  sa.n[5] = 2 * E_ * E_;
    sa.src[6] = pw2_w;   sa.hi[6] = whi + OFF_PW2_W;  sa.lo[6] = wlo + OFF_PW2_W;  sa.n[6] = E_ * E_;
    sa.src[7] = ff_w1;   sa.hi[7] = whi + OFF_FF_W1;  sa.lo[7] = wlo + OFF_FF_W1;  sa.n[7] = DFF_ * E_;
    sa.src[8] = ff_w2;   sa.hi[8] = whi + OFF_FF_W2;  sa.lo[8] = wlo + OFF_FF_W2;  sa.n[8] = E_ * DFF_;
    sa.src[9] = pos_emb; sa.hi[9] = whi + OFF_POSE;   sa.lo[9] = wlo + OFF_POSE;   sa.n[9] = PLEN * E_;
    sa.src[10] = src;    sa.hi[10] = ahi;             sa.lo[10] = alo;             sa.n[10] = NTOK * E_;
    split_multi_kernel<<<dim3(8192, NSEG), 256>>>(sa);

    // 1) macaron FFN
    gemm_mma_kernel<EPI_DSWISH, 0, 1><<<dim3(DFF_ / 128, NTOK / 128), 256, GEMM_SMEM_B>>>(
        ahi, alo, whi + OFF_FFM_W1, wlo + OFF_FFM_W1, ffm_b1, nullptr,
        nullptr, bhi, blo, NTOK, DFF_, E_);
    gemm_mma64_kernel<EPI_RES, 1, 1><<<dim3(E_ / 64, NTOK / 128), 256, GEMM64_SMEM_B>>>(
        bhi, blo, whi + OFF_FFM_W2, wlo + OFF_FFM_W2, ffm_b2, src,
        x1, ahi, alo, NTOK, E_, DFF_);

    // 2) attention
    gemm_mma_kernel<EPI_NONE, 1, 0><<<dim3((3 * E_) / 128, NTOK / 128), 256, GEMM_SMEM_B>>>(
        ahi, alo, whi + OFF_IN_W, wlo + OFF_IN_W, in_b, nullptr,
        qkv, nullptr, nullptr, NTOK, 3 * E_, E_);
    gemm_mma64_kernel<EPI_NONE, 1, 0><<<dim3(E_ / 64, (PLEN + 127) / 128), 256, GEMM64_SMEM_B>>>(
        whi + OFF_POSE, wlo + OFF_POSE, whi + OFF_WPOS, wlo + OFF_WPOS, nullptr, nullptr,
        pp, nullptr, nullptr, PLEN, E_, E_);
    attn_fused_kernel<<<dim3(T_ / 64, B_ * H_), 256, ATTN_SMEM>>>(qkv, pp, u, v, bhi, blo);
    gemm_mma64_kernel<EPI_RES, 1, 1><<<dim3(E_ / 64, NTOK / 128), 256, GEMM64_SMEM_B>>>(
        bhi, blo, whi + OFF_OUT_W, wlo + OFF_OUT_W, out_b, x1,
        x2, ahi, alo, NTOK, E_, E_);

    // 3) conv module
    gemm_mma_kernel<EPI_NONE, 1, 0><<<dim3((2 * E_) / 128, NTOK / 128), 256, GEMM_SMEM_B>>>(
        ahi, alo, whi + OFF_PW1_W, wlo + OFF_PW1_W, pw1_b, nullptr,
        ff, nullptr, nullptr, NTOK, 2 * E_, E_);
    glu_kernel<<<(NTOK * E_) / 256, 256>>>(ff, glu);
    dwconv_kernel<<<(NTOK * E_) / 256, 256>>>(glu, dw_w, dw_b, bhi, blo);
    gemm_mma64_kernel<EPI_RES, 1, 1><<<dim3(E_ / 64, NTOK / 128), 256, GEMM64_SMEM_B>>>(
        bhi, blo, whi + OFF_PW2_W, wlo + OFF_PW2_W, pw2_b, x2,
        x3, ahi, alo, NTOK, E_, E_);

    // 4) second FFN
    gemm_mma_kernel<EPI_DSWISH, 0, 1><<<dim3(DFF_ / 128, NTOK / 128), 256, GEMM_SMEM_B>>>(
        ahi, alo, whi + OFF_FF_W1, wlo + OFF_FF_W1, ff_b1, nullptr,
        nullptr, bhi, blo, NTOK, DFF_, E_);
    gemm_mma64_kernel<EPI_RES, 1, 0><<<dim3(E_ / 64, NTOK / 128), 256, GEMM64_SMEM_B>>>(
        bhi, blo, whi + OFF_FF_W2, wlo + OFF_FF_W2, ff_b2, x3,
        x1, nullptr, nullptr, NTOK, E_, DFF_);

    // 5) BasicNorm -> output
    basic_norm_kernel<<<NTOK, 256>>>(x1, leps, (float*)d_out);
}

// round 13
// speedup vs baseline: 1.0570x; 1.0570x over previous
#include <cuda_runtime.h>
#include <cuda_bf16.h>
#include <math.h>
#include <stdint.h>

// ---------------- problem dims ----------------
#define T_    1024
#define B_    4
#define E_    512
#define H_    8
#define D_    64
#define DFF_  2048
#define NTOK  4096
#define PLEN  2047
#define KCONV 31

typedef unsigned long long u64;

// ---------------- scratch ----------------
__device__ float g_ff[NTOK * DFF_];
__device__ float g_x1[NTOK * E_];
__device__ float g_x2[NTOK * E_];
__device__ float g_x3[NTOK * E_];
__device__ float g_qkv[NTOK * 3 * E_];
__device__ float g_pproj[PLEN * E_];
__device__ float g_glu[NTOK * E_];
__device__ __nv_bfloat16 g_whi[7339520];
__device__ __nv_bfloat16 g_wlo[7339520];
__device__ __nv_bfloat16 g_ahi[NTOK * DFF_];
__device__ __nv_bfloat16 g_alo[NTOK * DFF_];
__device__ __nv_bfloat16 g_bhi[NTOK * DFF_];
__device__ __nv_bfloat16 g_blo[NTOK * DFF_];

// packed weight offsets (elements)
#define OFF_FFM_W1 0
#define OFF_FFM_W2 1048576
#define OFF_IN_W   2097152
#define OFF_WPOS   2883584
#define OFF_OUT_W  3145728
#define OFF_PW1_W  3407872
#define OFF_PW2_W  3932160
#define OFF_FF_W1  4194304
#define OFF_FF_W2  5242880
#define OFF_POSE   6291456

__device__ __forceinline__ float sigmoidf_(float x) { return 1.f / (1.f + __expf(-x)); }

// ---------------- packed f32x2 helpers ----------------
__device__ __forceinline__ u64 pack2_(float lo, float hi) {
    u64 r; asm("mov.b64 %0, {%1, %2};" : "=l"(r) : "f"(lo), "f"(hi)); return r;
}
__device__ __forceinline__ u64 pdup_(float x) {
    u64 r; asm("mov.b64 %0, {%1, %1};" : "=l"(r) : "f"(x)); return r;
}
__device__ __forceinline__ u64 ffma2_(u64 a, u64 b, u64 c) {
    u64 d; asm("fma.rn.f32x2 %0, %1, %2, %3;" : "=l"(d) : "l"(a), "l"(b), "l"(c)); return d;
}
__device__ __forceinline__ u64 mul2_(u64 a, u64 b) {
    u64 d; asm("mul.rn.f32x2 %0, %1, %2;" : "=l"(d) : "l"(a), "l"(b)); return d;
}
__device__ __forceinline__ float2 unpack2_(u64 v) {
    float2 f; asm("mov.b64 {%0, %1}, %2;" : "=f"(f.x), "=f"(f.y) : "l"(v)); return f;
}
__device__ __forceinline__ uint32_t smem_u32_(const void* p) {
    return (uint32_t)__cvta_generic_to_shared(p);
}
__device__ __forceinline__ void cpasync16_(uint32_t dst, const void* src, int srcbytes) {
    asm volatile("cp.async.ca.shared.global [%0], [%1], 16, %2;"
                 :: "r"(dst), "l"(src), "r"(srcbytes));
}
__device__ __forceinline__ void split2_(float v0, float v1,
                                        __nv_bfloat16* hi, __nv_bfloat16* lo, size_t off) {
    __nv_bfloat16 h0 = __float2bfloat16(v0);
    __nv_bfloat16 h1 = __float2bfloat16(v1);
    __nv_bfloat162 hp; hp.x = h0; hp.y = h1;
    __nv_bfloat162 lp;
    lp.x = __float2bfloat16(v0 - __bfloat162float(h0));
    lp.y = __float2bfloat16(v1 - __bfloat162float(h1));
    *(__nv_bfloat162*)(hi + off) = hp;
    *(__nv_bfloat162*)(lo + off) = lp;
}

// ---------------- multi-segment hi/lo split ----------------
#define NSEG 11
struct SplitArgs {
    const float* src[NSEG];
    __nv_bfloat16* hi[NSEG];
    __nv_bfloat16* lo[NSEG];
    int n[NSEG];
};

__global__ void split_multi_kernel(SplitArgs a)
{
    int seg = blockIdx.y;
    int i = blockIdx.x * 256 + threadIdx.x;
    if (i >= a.n[seg]) return;
    float x = a.src[seg][i];
    __nv_bfloat16 h = __float2bfloat16(x);
    a.hi[seg][i] = h;
    a.lo[seg][i] = __float2bfloat16(x - __bfloat162float(h));
}

// ---------------- bf16 mma.sync NT GEMM: 128x128, fused 3-term, 2 CTAs/SM ----------------
enum { EPI_NONE = 0, EPI_DSWISH = 1, EPI_RES = 2 };
#define SSTRIDE 40
#define TILE_E  (128 * SSTRIDE)
#define STAGE_E (4 * TILE_E)
#define GEMM_SMEM_B (2 * STAGE_E * 2)    // 81920 bytes

template <int EPI, int WC, int WS>
__global__ void __launch_bounds__(256, 2)
gemm_mma_kernel(const __nv_bfloat16* __restrict__ Ahi, const __nv_bfloat16* __restrict__ Alo,
                const __nv_bfloat16* __restrict__ Bhi, const __nv_bfloat16* __restrict__ Blo,
                const float* __restrict__ bias, const float* __restrict__ res,
                float* __restrict__ C,
                __nv_bfloat16* __restrict__ Ohi, __nv_bfloat16* __restrict__ Olo,
                int M, int N, int K)
{
    extern __shared__ __nv_bfloat16 smem_g[];

    const int tid = threadIdx.x;
    const int wid = tid >> 5;
    const int lane = tid & 31;
    const int m0 = blockIdx.y * 128, n0 = blockIdx.x * 128;
    const int nk = K >> 5;

    const int mw = (wid & 1) * 64;
    const int nw = (wid >> 1) * 32;

    float acc[4][4][4];
#pragma unroll
    for (int a = 0; a < 4; a++)
#pragma unroll
        for (int b = 0; b < 4; b++)
#pragma unroll
            for (int c = 0; c < 4; c++) acc[a][b][c] = 0.f;

    const int r0 = tid >> 2,         col0 = (tid & 3) << 3;
    const int r1 = (tid + 256) >> 2, col1 = ((tid + 256) & 3) << 3;
    const uint32_t s_u = smem_u32_(smem_g);
    const uint32_t d0 = (uint32_t)(r0 * SSTRIDE + col0) * 2;
    const uint32_t d1 = (uint32_t)(r1 * SSTRIDE + col1) * 2;
    const int am0 = m0 + r0, am1 = m0 + r1;
    const int asz0 = am0 < M ? 16 : 0;
    const int asz1 = am1 < M ? 16 : 0;
    const size_t arow0 = (size_t)(am0 < M ? am0 : 0) * K;
    const size_t arow1 = (size_t)(am1 < M ? am1 : 0) * K;
    const size_t brow0 = (size_t)(n0 + r0) * K;
    const size_t brow1 = (size_t)(n0 + r1) * K;

    auto issue_loads = [&](int kt) {
        int kk0 = kt << 5;
        uint32_t so = (kt & 1) ? (uint32_t)STAGE_E * 2 : 0u;
        cpasync16_(s_u + so + d0, Ahi + arow0 + kk0 + col0, asz0);
        cpasync16_(s_u + so + d1, Ahi + arow1 + kk0 + col1, asz1);
        cpasync16_(s_u + so + TILE_E * 2 + d0, Alo + arow0 + kk0 + col0, asz0);
        cpasync16_(s_u + so + TILE_E * 2 + d1, Alo + arow1 + kk0 + col1, asz1);
        cpasync16_(s_u + so + 2 * TILE_E * 2 + d0, Bhi + brow0 + kk0 + col0, 16);
        cpasync16_(s_u + so + 2 * TILE_E * 2 + d1, Bhi + brow1 + kk0 + col1, 16);
        cpasync16_(s_u + so + 3 * TILE_E * 2 + d0, Blo + brow0 + kk0 + col0, 16);
        cpasync16_(s_u + so + 3 * TILE_E * 2 + d1, Blo + brow1 + kk0 + col1, 16);
    };

    issue_loads(0);
    asm volatile("cp.async.commit_group;" ::: "memory");

    const int lr8 = lane & 7;
    const int sel = lane >> 3;

#define MMA_(AH, BF)                                                            \
            _Pragma("unroll")                                                   \
            for (int mt = 0; mt < 4; mt++) {                                    \
                _Pragma("unroll")                                               \
                for (int nt = 0; nt < 4; nt++) {                                \
                    uint32_t b0 = BF[nt >> 1][(nt & 1) * 2 + 0];                \
                    uint32_t b1 = BF[nt >> 1][(nt & 1) * 2 + 1];                \
                    asm volatile(                                               \
                        "mma.sync.aligned.m16n8k16.row.col.f32.bf16.bf16.f32 "  \
                        "{%0,%1,%2,%3}, {%4,%5,%6,%7}, {%8,%9}, {%0,%1,%2,%3};" \
                        : "+f"(acc[mt][nt][0]), "+f"(acc[mt][nt][1]),           \
                          "+f"(acc[mt][nt][2]), "+f"(acc[mt][nt][3])            \
                        : "r"(AH[mt][0]), "r"(AH[mt][1]),                       \
                          "r"(AH[mt][2]), "r"(AH[mt][3]),                       \
                          "r"(b0), "r"(b1));                                    \
                }                                                               \
            }

    for (int kt = 0; kt < nk; kt++) {
        if (kt + 1 < nk) issue_loads(kt + 1);
        asm volatile("cp.async.commit_group;" ::: "memory");
        asm volatile("cp.async.wait_group 1;" ::: "memory");
        __syncthreads();

        const uint32_t base = s_u + ((kt & 1) ? (uint32_t)STAGE_E * 2 : 0u);
#pragma unroll
        for (int kk = 0; kk < 2; kk++) {
            uint32_t ahi[4][4];
#pragma unroll
            for (int mt = 0; mt < 4; mt++) {
                int row = mw + mt * 16 + lr8 + (sel & 1) * 8;
                int col = kk * 16 + (sel >> 1) * 8;
                uint32_t addr = base + (uint32_t)(row * SSTRIDE + col) * 2;
                asm volatile("ldmatrix.sync.aligned.m8n8.x4.shared.b16 {%0,%1,%2,%3}, [%4];"
                             : "=r"(ahi[mt][0]), "=r"(ahi[mt][1]), "=r"(ahi[mt][2]), "=r"(ahi[mt][3])
                             : "r"(addr));
            }
            uint32_t bfr[2][4];
#pragma unroll
            for (int np = 0; np < 2; np++) {
                int row = nw + np * 16 + lr8 + (sel >> 1) * 8;
                int col = kk * 16 + (sel & 1) * 8;
                uint32_t addr = base + 2 * TILE_E * 2 + (uint32_t)(row * SSTRIDE + col) * 2;
                asm volatile("ldmatrix.sync.aligned.m8n8.x4.shared.b16 {%0,%1,%2,%3}, [%4];"
                             : "=r"(bfr[np][0]), "=r"(bfr[np][1]), "=r"(bfr[np][2]), "=r"(bfr[np][3])
                             : "r"(addr));
            }
            MMA_(ahi, bfr)

            {
                uint32_t alo[4][4];
#pragma unroll
                for (int mt = 0; mt < 4; mt++) {
                    int row = mw + mt * 16 + lr8 + (sel & 1) * 8;
                    int col = kk * 16 + (sel >> 1) * 8;
                    uint32_t addr = base + TILE_E * 2 + (uint32_t)(row * SSTRIDE + col) * 2;
                    asm volatile("ldmatrix.sync.aligned.m8n8.x4.shared.b16 {%0,%1,%2,%3}, [%4];"
                                 : "=r"(alo[mt][0]), "=r"(alo[mt][1]), "=r"(alo[mt][2]), "=r"(alo[mt][3])
                                 : "r"(addr));
                }
                MMA_(alo, bfr)
            }

#pragma unroll
            for (int np = 0; np < 2; np++) {
                int row = nw + np * 16 + lr8 + (sel >> 1) * 8;
                int col = kk * 16 + (sel & 1) * 8;
                uint32_t addr = base + 3 * TILE_E * 2 + (uint32_t)(row * SSTRIDE + col) * 2;
                asm volatile("ldmatrix.sync.aligned.m8n8.x4.shared.b16 {%0,%1,%2,%3}, [%4];"
                             : "=r"(bfr[np][0]), "=r"(bfr[np][1]), "=r"(bfr[np][2]), "=r"(bfr[np][3])
                             : "r"(addr));
            }
            MMA_(ahi, bfr)
        }
        __syncthreads();
    }
#undef MMA_

    const int g = lane >> 2, t4 = lane & 3;
#pragma unroll
    for (int mt = 0; mt < 4; mt++) {
#pragma unroll
        for (int rr = 0; rr < 2; rr++) {
            int row = m0 + mw + mt * 16 + g + rr * 8;
            if (row >= M) continue;
#pragma unroll
            for (int nt = 0; nt < 4; nt++) {
                int col = n0 + nw + nt * 8 + t4 * 2;
                float v0 = acc[mt][nt][rr * 2 + 0];
                float v1 = acc[mt][nt][rr * 2 + 1];
                if (bias) { v0 += bias[col]; v1 += bias[col + 1]; }
                if (EPI == EPI_DSWISH) {
                    v0 = v0 * sigmoidf_(v0 - 1.f);
                    v1 = v1 * sigmoidf_(v1 - 1.f);
                }
                size_t off = (size_t)row * N + col;
                if (EPI == EPI_RES) {
                    float2 rv = *(const float2*)&res[off];
                    v0 += rv.x; v1 += rv.y;
                }
                if (WC) *(float2*)&C[off] = make_float2(v0, v1);
                if (WS) split2_(v0, v1, Ohi, Olo, off);
            }
        }
    }
}

// ---------------- split-K=2 variant: raw fp32 partials ----------------
__global__ void __launch_bounds__(256, 2)
gemm_mma_sk_kernel(const __nv_bfloat16* __restrict__ Ahi, const __nv_bfloat16* __restrict__ Alo,
                   const __nv_bfloat16* __restrict__ Bhi, const __nv_bfloat16* __restrict__ Blo,
                   float* __restrict__ Cpart, int M, int N, int K)
{
    extern __shared__ __nv_bfloat16 smem_g[];

    const int tid = threadIdx.x;
    const int wid = tid >> 5;
    const int lane = tid & 31;
    const int m0 = blockIdx.y * 128, n0 = blockIdx.x * 128;
    const int nk2 = (K >> 5) >> 1;
    const int ktb = blockIdx.z * nk2;

    const int mw = (wid & 1) * 64;
    const int nw = (wid >> 1) * 32;

    float acc[4][4][4];
#pragma unroll
    for (int a = 0; a < 4; a++)
#pragma unroll
        for (int b = 0; b < 4; b++)
#pragma unroll
            for (int c = 0; c < 4; c++) acc[a][b][c] = 0.f;

    const int r0 = tid >> 2,         col0 = (tid & 3) << 3;
    const int r1 = (tid + 256) >> 2, col1 = ((tid + 256) & 3) << 3;
    const uint32_t s_u = smem_u32_(smem_g);
    const uint32_t d0 = (uint32_t)(r0 * SSTRIDE + col0) * 2;
    const uint32_t d1 = (uint32_t)(r1 * SSTRIDE + col1) * 2;
    const size_t arow0 = (size_t)(m0 + r0) * K;
    const size_t arow1 = (size_t)(m0 + r1) * K;
    const size_t brow0 = (size_t)(n0 + r0) * K;
    const size_t brow1 = (size_t)(n0 + r1) * K;

    auto issue_loads = [&](int kt) {
        int kk0 = (ktb + kt) << 5;
        uint32_t so = (kt & 1) ? (uint32_t)STAGE_E * 2 : 0u;
        cpasync16_(s_u + so + d0, Ahi + arow0 + kk0 + col0, 16);
        cpasync16_(s_u + so + d1, Ahi + arow1 + kk0 + col1, 16);
        cpasync16_(s_u + so + TILE_E * 2 + d0, Alo + arow0 + kk0 + col0, 16);
        cpasync16_(s_u + so + TILE_E * 2 + d1, Alo + arow1 + kk0 + col1, 16);
        cpasync16_(s_u + so + 2 * TILE_E * 2 + d0, Bhi + brow0 + kk0 + col0, 16);
        cpasync16_(s_u + so + 2 * TILE_E * 2 + d1, Bhi + brow1 + kk0 + col1, 16);
        cpasync16_(s_u + so + 3 * TILE_E * 2 + d0, Blo + brow0 + kk0 + col0, 16);
        cpasync16_(s_u + so + 3 * TILE_E * 2 + d1, Blo + brow1 + kk0 + col1, 16);
    };

    issue_loads(0);
    asm volatile("cp.async.commit_group;" ::: "memory");

    const int lr8 = lane & 7;
    const int sel = lane >> 3;

#define MMA_(AH, BF)                                                            \
            _Pragma("unroll")                                                   \
            for (int mt = 0; mt < 4; mt++) {                                    \
                _Pragma("unroll")                                               \
                for (int nt = 0; nt < 4; nt++) {                                \
                    uint32_t b0 = BF[nt >> 1][(nt & 1) * 2 + 0];                \
                    uint32_t b1 = BF[nt >> 1][(nt & 1) * 2 + 1];                \
                    asm volatile(                                               \
                        "mma.sync.aligned.m16n8k16.row.col.f32.bf16.bf16.f32 "  \
                        "{%0,%1,%2,%3}, {%4,%5,%6,%7}, {%8,%9}, {%0,%1,%2,%3};" \
                        : "+f"(acc[mt][nt][0]), "+f"(acc[mt][nt][1]),           \
                          "+f"(acc[mt][nt][2]), "+f"(acc[mt][nt][3])            \
                        : "r"(AH[mt][0]), "r"(AH[mt][1]),                       \
                          "r"(AH[mt][2]), "r"(AH[mt][3]),                       \
                          "r"(b0), "r"(b1));                                    \
                }                                                               \
            }

    for (int kt = 0; kt < nk2; kt++) {
        if (kt + 1 < nk2) issue_loads(kt + 1);
        asm volatile("cp.async.commit_group;" ::: "memory");
        asm volatile("cp.async.wait_group 1;" ::: "memory");
        __syncthreads();

        const uint32_t base = s_u + ((kt & 1) ? (uint32_t)STAGE_E * 2 : 0u);
#pragma unroll
        for (int kk = 0; kk < 2; kk++) {
            uint32_t ahi[4][4];
#pragma unroll
            for (int mt = 0; mt < 4; mt++) {
                int row = mw + mt * 16 + lr8 + (sel & 1) * 8;
                int col = kk * 16 + (sel >> 1) * 8;
                uint32_t addr = base + (uint32_t)(row * SSTRIDE + col) * 2;
                asm volatile("ldmatrix.sync.aligned.m8n8.x4.shared.b16 {%0,%1,%2,%3}, [%4];"
                             : "=r"(ahi[mt][0]), "=r"(ahi[mt][1]), "=r"(ahi[mt][2]), "=r"(ahi[mt][3])
                             : "r"(addr));
            }
            uint32_t bfr[2][4];
#pragma unroll
            for (int np = 0; np < 2; np++) {
                int row = nw + np * 16 + lr8 + (sel >> 1) * 8;
                int col = kk * 16 + (sel & 1) * 8;
                uint32_t addr = base + 2 * TILE_E * 2 + (uint32_t)(row * SSTRIDE + col) * 2;
                asm volatile("ldmatrix.sync.aligned.m8n8.x4.shared.b16 {%0,%1,%2,%3}, [%4];"
                             : "=r"(bfr[np][0]), "=r"(bfr[np][1]), "=r"(bfr[np][2]), "=r"(bfr[np][3])
                             : "r"(addr));
            }
            MMA_(ahi, bfr)

            {
                uint32_t alo[4][4];
#pragma unroll
                for (int mt = 0; mt < 4; mt++) {
                    int row = mw + mt * 16 + lr8 + (sel & 1) * 8;
                    int col = kk * 16 + (sel >> 1) * 8;
                    uint32_t addr = base + TILE_E * 2 + (uint32_t)(row * SSTRIDE + col) * 2;
                    asm volatile("ldmatrix.sync.aligned.m8n8.x4.shared.b16 {%0,%1,%2,%3}, [%4];"
                                 : "=r"(alo[mt][0]), "=r"(alo[mt][1]), "=r"(alo[mt][2]), "=r"(alo[mt][3])
                                 : "r"(addr));
                }
                MMA_(alo, bfr)
            }

#pragma unroll
            for (int np = 0; np < 2; np++) {
                int row = nw + np * 16 + lr8 + (sel >> 1) * 8;
                int col = kk * 16 + (sel & 1) * 8;
                uint32_t addr = base + 3 * TILE_E * 2 + (uint32_t)(row * SSTRIDE + col) * 2;
                asm volatile("ldmatrix.sync.aligned.m8n8.x4.shared.b16 {%0,%1,%2,%3}, [%4];"
                             : "=r"(bfr[np][0]), "=r"(bfr[np][1]), "=r"(bfr[np][2]), "=r"(bfr[np][3])
                             : "r"(addr));
            }
            MMA_(ahi, bfr)
        }
        __syncthreads();
    }
#undef MMA_

    float* Cp = Cpart + (size_t)blockIdx.z * M * N;
    const int g = lane >> 2, t4 = lane & 3;
#pragma unroll
    for (int mt = 0; mt < 4; mt++) {
#pragma unroll
        for (int rr = 0; rr < 2; rr++) {
            int row = m0 + mw + mt * 16 + g + rr * 8;
#pragma unroll
            for (int nt = 0; nt < 4; nt++) {
                int col = n0 + nw + nt * 8 + t4 * 2;
                size_t off = (size_t)row * N + col;
                *(float2*)&Cp[off] = make_float2(acc[mt][nt][rr * 2 + 0],
                                                 acc[mt][nt][rr * 2 + 1]);
            }
        }
    }
}

// ---------------- split-K combine: C = part0 + part1 + bias + res ----------------
template <int WS, int WC>
__global__ void combine_kernel(const float* __restrict__ part, const float* __restrict__ bias,
                               const float* __restrict__ res, float* __restrict__ C,
                               __nv_bfloat16* __restrict__ Ohi, __nv_bfloat16* __restrict__ Olo)
{
    int i2 = blockIdx.x * 256 + threadIdx.x;
    if (i2 >= NTOK * E_ / 2) return;
    size_t off = (size_t)i2 * 2;
    int col = (int)(off & (E_ - 1));
    float2 p0 = *(const float2*)&part[off];
    float2 p1 = *(const float2*)&part[off + (size_t)NTOK * E_];
    float2 rv = *(const float2*)&res[off];
    float v0 = p0.x + p1.x + bias[col] + rv.x;
    float v1 = p0.y + p1.y + bias[col + 1] + rv.y;
    if (WC) *(float2*)&C[off] = make_float2(v0, v1);
    if (WS) split2_(v0, v1, Ohi, Olo, off);
}

// ---------------- fused attention (transposed Qu/Kt, 2 CTAs/SM) ----------------
#define ATTN_SMEM ((64 * 68 + 64 + 64 * 68 + 64 * 128 + 64 * 68 + 64 * 68) * 4)

__global__ void __launch_bounds__(256, 2)
attn_fused_kernel(const float* __restrict__ qkv,
                  const float* __restrict__ pproj,
                  const float* __restrict__ u,
                  const float* __restrict__ v,
                  __nv_bfloat16* __restrict__ chi,
                  __nv_bfloat16* __restrict__ clo)
{
    extern __shared__ float sm[];
    float* Qu  = sm;
    float* duv = Qu + 64 * 68;
    float* Kt  = duv + 64;
    float* Ps  = Kt + 64 * 68;
    float* Vs  = Ps + 64 * 128;
    float* Es  = Vs + 64 * 68;

    const int bh = blockIdx.y;
    const int b = bh >> 3, h = bh & 7;
    const int i0 = blockIdx.x * 64;
    const int tid = threadIdx.x;
    const float scale = 0.125f;

    for (int idx = tid; idx < 64 * 64; idx += 256) {
        int li = idx >> 6, d = idx & 63;
        float q = qkv[(size_t)((i0 + li) * B_ + b) * (3 * E_) + h * 64 + d] * scale;
        Qu[d * 68 + li] = q + u[h * 64 + d];
    }
    if (tid < 64) duv[tid] = v[h * 64 + tid] - u[h * 64 + tid];

    const int tm = (tid >> 4) << 2;
    const int tn = (tid & 15) << 2;
    const int base = 63 - tm + tn;

    float mrow[4], lrow[4];
#pragma unroll
    for (int i = 0; i < 4; i++) { mrow[i] = -1e30f; lrow[i] = 0.f; }
    u64 outacc[4][2];
#pragma unroll
    for (int i = 0; i < 4; i++) { outacc[i][0] = 0ull; outacc[i][1] = 0ull; }

    for (int j0 = 0; j0 < T_; j0 += 64) {
        __syncthreads();
        for (int idx = tid; idx < 64 * 64; idx += 256) {
            int li = idx >> 6, d = idx & 63;
            size_t rb = (size_t)((j0 + li) * B_ + b) * (3 * E_) + h * 64 + d;
            Kt[d * 68 + li] = qkv[rb + E_];
            Vs[li * 68 + d] = qkv[rb + 2 * E_];
        }
        const int m_min = 960 - i0 + j0;
        for (int idx = tid; idx < 64 * 127; idx += 256) {
            int d = idx / 127, mm = idx % 127;
            Ps[d * 128 + mm] = pproj[(size_t)(m_min + mm) * E_ + h * 64 + d];
        }
        __syncthreads();

        u64 acc2[4][2];
#pragma unroll
        for (int i = 0; i < 4; i++) { acc2[i][0] = 0ull; acc2[i][1] = 0ull; }

#pragma unroll 4
        for (int d = 0; d < 64; d++) {
            float duvd = duv[d];
            float4 qu4 = *(const float4*)&Qu[d * 68 + tm];
            float4 kt4 = *(const float4*)&Kt[d * 68 + tn];
            u64 ad[4], cd[4];
            ad[0] = pdup_(qu4.x); cd[0] = pdup_(qu4.x + duvd);
            ad[1] = pdup_(qu4.y); cd[1] = pdup_(qu4.y + duvd);
            ad[2] = pdup_(qu4.z); cd[2] = pdup_(qu4.z + duvd);
            ad[3] = pdup_(qu4.w); cd[3] = pdup_(qu4.w + duvd);
            u64 kb0 = pack2_(kt4.x, kt4.y), kb1 = pack2_(kt4.z, kt4.w);
            float p7[7];
#pragma unroll
            for (int t = 0; t < 7; t++) p7[t] = Ps[d * 128 + base + t - 3];
            u64 pp[6];
#pragma unroll
            for (int t = 0; t < 6; t++) pp[t] = pack2_(p7[t], p7[t + 1]);
#pragma unroll
            for (int ii = 0; ii < 4; ii++) {
                acc2[ii][0] = ffma2_(ad[ii], kb0, acc2[ii][0]);
                acc2[ii][1] = ffma2_(ad[ii], kb1, acc2[ii][1]);
                acc2[ii][0] = ffma2_(cd[ii], pp[3 - ii], acc2[ii][0]);
                acc2[ii][1] = ffma2_(cd[ii], pp[5 - ii], acc2[ii][1]);
            }
        }

#pragma unroll
        for (int ii = 0; ii < 4; ii++) {
            float2 t0 = unpack2_(acc2[ii][0]);
            float2 t1 = unpack2_(acc2[ii][1]);
            float s0 = t0.x, s1 = t0.y, s2 = t1.x, s3 = t1.y;
            float mx = fmaxf(fmaxf(s0, s1), fmaxf(s2, s3));
#pragma unroll
            for (int o = 1; o < 16; o <<= 1)
                mx = fmaxf(mx, __shfl_xor_sync(0xffffffffu, mx, o));
            float mnew = fmaxf(mrow[ii], mx);
            float alpha = __expf(mrow[ii] - mnew);
            mrow[ii] = mnew;
            s0 = __expf(s0 - mnew); s1 = __expf(s1 - mnew);
            s2 = __expf(s2 - mnew); s3 = __expf(s3 - mnew);
            float rs = s0 + s1 + s2 + s3;
#pragma unroll
            for (int o = 1; o < 16; o <<= 1)
                rs += __shfl_xor_sync(0xffffffffu, rs, o);
            lrow[ii] = lrow[ii] * alpha + rs;
            u64 al = pdup_(alpha);
            outacc[ii][0] = mul2_(outacc[ii][0], al);
            outacc[ii][1] = mul2_(outacc[ii][1], al);
            *(float4*)&Es[(tm + ii) * 68 + tn] = make_float4(s0, s1, s2, s3);
        }
        __syncthreads();

#pragma unroll 8
        for (int kk = 0; kk < 64; kk++) {
            ulonglong2 bq = *(const ulonglong2*)&Vs[kk * 68 + tn];
#pragma unroll
            for (int ii = 0; ii < 4; ii++) {
                u64 a = pdup_(Es[(tm + ii) * 68 + kk]);
                outacc[ii][0] = ffma2_(a, bq.x, outacc[ii][0]);
                outacc[ii][1] = ffma2_(a, bq.y, outacc[ii][1]);
            }
        }
    }

#pragma unroll
    for (int ii = 0; ii < 4; ii++) {
        float inv = 1.f / lrow[ii];
        float2 t0 = unpack2_(outacc[ii][0]);
        float2 t1 = unpack2_(outacc[ii][1]);
        size_t off = (size_t)((i0 + tm + ii) * B_ + b) * E_ + h * 64 + tn;
        split2_(t0.x * inv, t0.y * inv, chi, clo, off);
        split2_(t1.x * inv, t1.y * inv, chi, clo, off + 2);
    }
}

// ---------------- GLU ----------------
__global__ void glu_kernel(const float* __restrict__ y, float* __restrict__ out)
{
    int idx = blockIdx.x * 256 + threadIdx.x;
    if (idx >= NTOK * E_) return;
    int r = idx >> 9, c = idx & 511;
    float a = y[(size_t)r * 1024 + c];
    float g = y[(size_t)r * 1024 + 512 + c];
    out[idx] = a * sigmoidf_(g);
}

// ---------------- depthwise conv + DoubleSwish -> split bf16 ----------------
__global__ void dwconv_kernel(const float* __restrict__ x, const float* __restrict__ w,
                              const float* __restrict__ bias,
                              __nv_bfloat16* __restrict__ ohi, __nv_bfloat16* __restrict__ olo)
{
    int idx = blockIdx.x * 256 + threadIdx.x;
    if (idx >= NTOK * E_) return;
    int c = idx & 511;
    int tb = idx >> 9;
    int t = tb >> 2, b = tb & 3;
    float acc = bias[c];
#pragma unroll
    for (int k = 0; k < KCONV; k++) {
        int tt = t + k - 15;
        if (tt >= 0 && tt < T_)
            acc += x[(size_t)(tt * B_ + b) * E_ + c] * w[c * KCONV + k];
    }
    float vv = acc * sigmoidf_(acc - 1.f);
    __nv_bfloat16 h = __float2bfloat16(vv);
    ohi[idx] = h;
    olo[idx] = __float2bfloat16(vv - __bfloat162float(h));
}

// ---------------- BasicNorm ----------------
__global__ void basic_norm_kernel(const float* __restrict__ x, const float* __restrict__ leps,
                                  float* __restrict__ out)
{
    __shared__ float red[8];
    const int tid = threadIdx.x;
    const float* p = x + (size_t)blockIdx.x * E_;
    float v0 = p[tid], v1 = p[tid + 256];
    float ss = v0 * v0 + v1 * v1;
#pragma unroll
    for (int o = 16; o > 0; o >>= 1) ss += __shfl_xor_sync(0xffffffffu, ss, o);
    if ((tid & 31) == 0) red[tid >> 5] = ss;
    __syncthreads();
    float tot = red[0];
#pragma unroll
    for (int i = 1; i < 8; i++) tot += red[i];
    float r = rsqrtf(tot * (1.f / (float)E_) + __expf(leps[0]));
    out[(size_t)blockIdx.x * E_ + tid]       = v0 * r;
    out[(size_t)blockIdx.x * E_ + tid + 256] = v1 * r;
}

// ---------------- launch ----------------
extern "C" void kernel_launch(void* const* d_in, const int* in_sizes, int n_in,
                              void* d_out, int out_size)
{
    const float* src      = (const float*)d_in[0];
    const float* pos_emb  = (const float*)d_in[1];
    const float* in_w     = (const float*)d_in[2];
    const float* in_b     = (const float*)d_in[3];
    const float* out_w    = (const float*)d_in[4];
    const float* out_b    = (const float*)d_in[5];
    const float* wpos     = (const float*)d_in[6];
    const float* u        = (const float*)d_in[7];
    const float* v        = (const float*)d_in[8];
    const float* ffm_w1   = (const float*)d_in[9];
    const float* ffm_b1   = (const float*)d_in[10];
    const float* ffm_w2   = (const float*)d_in[11];
    const float* ffm_b2   = (const float*)d_in[12];
    const float* ff_w1    = (const float*)d_in[13];
    const float* ff_b1    = (const float*)d_in[14];
    const float* ff_w2    = (const float*)d_in[15];
    const float* ff_b2    = (const float*)d_in[16];
    const float* pw1_w    = (const float*)d_in[17];
    const float* pw1_b    = (const float*)d_in[18];
    const float* dw_w     = (const float*)d_in[19];
    const float* dw_b     = (const float*)d_in[20];
    const float* pw2_w    = (const float*)d_in[21];
    const float* pw2_b    = (const float*)d_in[22];
    const float* leps     = (const float*)d_in[23];

    float *ff, *x1, *x2, *x3, *qkv, *pp, *glu;
    __nv_bfloat16 *whi, *wlo, *ahi, *alo, *bhi, *blo;
    cudaGetSymbolAddress((void**)&ff,  g_ff);
    cudaGetSymbolAddress((void**)&x1,  g_x1);
    cudaGetSymbolAddress((void**)&x2,  g_x2);
    cudaGetSymbolAddress((void**)&x3,  g_x3);
    cudaGetSymbolAddress((void**)&qkv, g_qkv);
    cudaGetSymbolAddress((void**)&pp,  g_pproj);
    cudaGetSymbolAddress((void**)&glu, g_glu);
    cudaGetSymbolAddress((void**)&whi, g_whi);
    cudaGetSymbolAddress((void**)&wlo, g_wlo);
    cudaGetSymbolAddress((void**)&ahi, g_ahi);
    cudaGetSymbolAddress((void**)&alo, g_alo);
    cudaGetSymbolAddress((void**)&bhi, g_bhi);
    cudaGetSymbolAddress((void**)&blo, g_blo);

    cudaFuncSetAttribute(attn_fused_kernel, cudaFuncAttributeMaxDynamicSharedMemorySize,
                         ATTN_SMEM);
#define SET_GSMEM(EPI, WC, WS) \
    cudaFuncSetAttribute((gemm_mma_kernel<EPI, WC, WS>), \
                         cudaFuncAttributeMaxDynamicSharedMemorySize, GEMM_SMEM_B)
    SET_GSMEM(EPI_DSWISH, 0, 1);
    SET_GSMEM(EPI_RES, 1, 1);
    SET_GSMEM(EPI_NONE, 1, 0);
#undef SET_GSMEM
    cudaFuncSetAttribute(gemm_mma_sk_kernel, cudaFuncAttributeMaxDynamicSharedMemorySize,
                         GEMM_SMEM_B);

    // launch 0: all splits in one kernel
    SplitArgs sa;
    sa.src[0] = ffm_w1;  sa.hi[0] = whi + OFF_FFM_W1; sa.lo[0] = wlo + OFF_FFM_W1; sa.n[0] = DFF_ * E_;
    sa.src[1] = ffm_w2;  sa.hi[1] = whi + OFF_FFM_W2; sa.lo[1] = wlo + OFF_FFM_W2; sa.n[1] = E_ * DFF_;
    sa.src[2] = in_w;    sa.hi[2] = whi + OFF_IN_W;   sa.lo[2] = wlo + OFF_IN_W;   sa.n[2] = 3 * E_ * E_;
    sa.src[3] = wpos;    sa.hi[3] = whi + OFF_WPOS;   sa.lo[3] = wlo + OFF_WPOS;   sa.n[3] = E_ * E_;
    sa.src[4] = out_w;   sa.hi[4] = whi + OFF_OUT_W;  sa.lo[4] = wlo + OFF_OUT_W;  sa.n[4] = E_ * E_;
    sa.src[5] = pw1_w;   sa.hi[5] = whi + OFF_PW1_W;  sa.lo[5] = wlo + OFF_PW1_W;  sa.n[5] = 2 * E_ * E_;
    sa.src[6] = pw2_w;   sa.hi[6] = whi + OFF_PW2_W;  sa.lo[6] = wlo + OFF_PW2_W;  sa.n[6] = E_ * E_;
    sa.src[7] = ff_w1;   sa.hi[7] = whi + OFF_FF_W1;  sa.lo[7] = wlo + OFF_FF_W1;  sa.n[7] = DFF_ * E_;
    sa.src[8] = ff_w2;   sa.hi[8] = whi + OFF_FF_W2;  sa.lo[8] = wlo + OFF_FF_W2;  sa.n[8] = E_ * DFF_;
    sa.src[9] = pos_emb; sa.hi[9] = whi + OFF_POSE;   sa.lo[9] = wlo + OFF_POSE;   sa.n[9] = PLEN * E_;
    sa.src[10] = src;    sa.hi[10] = ahi;             sa.lo[10] = alo;             sa.n[10] = NTOK * E_;
    split_multi_kernel<<<dim3(8192, NSEG), 256>>>(sa);

    // 1) macaron FFN (FFN2 via split-K)
    gemm_mma_kernel<EPI_DSWISH, 0, 1><<<dim3(DFF_ / 128, NTOK / 128), 256, GEMM_SMEM_B>>>(
        ahi, alo, whi + OFF_FFM_W1, wlo + OFF_FFM_W1, ffm_b1, nullptr,
        nullptr, bhi, blo, NTOK, DFF_, E_);
    gemm_mma_sk_kernel<<<dim3(E_ / 128, NTOK / 128, 2), 256, GEMM_SMEM_B>>>(
        bhi, blo, whi + OFF_FFM_W2, wlo + OFF_FFM_W2, ff, NTOK, E_, DFF_);
    combine_kernel<1, 1><<<(NTOK * E_ / 2 + 255) / 256, 256>>>(
        ff, ffm_b2, src, x1, ahi, alo);

    // 2) attention
    gemm_mma_kernel<EPI_NONE, 1, 0><<<dim3((3 * E_) / 128, NTOK / 128), 256, GEMM_SMEM_B>>>(
        ahi, alo, whi + OFF_IN_W, wlo + OFF_IN_W, in_b, nullptr,
        qkv, nullptr, nullptr, NTOK, 3 * E_, E_);
    gemm_mma_kernel<EPI_NONE, 1, 0><<<dim3(E_ / 128, (PLEN + 127) / 128), 256, GEMM_SMEM_B>>>(
        whi + OFF_POSE, wlo + OFF_POSE, whi + OFF_WPOS, wlo + OFF_WPOS, nullptr, nullptr,
        pp, nullptr, nullptr, PLEN, E_, E_);
    attn_fused_kernel<<<dim3(T_ / 64, B_ * H_), 256, ATTN_SMEM>>>(qkv, pp, u, v, bhi, blo);
    gemm_mma_kernel<EPI_RES, 1, 1><<<dim3(E_ / 128, NTOK / 128), 256, GEMM_SMEM_B>>>(
        bhi, blo, whi + OFF_OUT_W, wlo + OFF_OUT_W, out_b, x1,
        x2, ahi, alo, NTOK, E_, E_);

    // 3) conv module
    gemm_mma_kernel<EPI_NONE, 1, 0><<<dim3((2 * E_) / 128, NTOK / 128), 256, GEMM_SMEM_B>>>(
        ahi, alo, whi + OFF_PW1_W, wlo + OFF_PW1_W, pw1_b, nullptr,
        ff, nullptr, nullptr, NTOK, 2 * E_, E_);
    glu_kernel<<<(NTOK * E_) / 256, 256>>>(ff, glu);
    dwconv_kernel<<<(NTOK * E_) / 256, 256>>>(glu, dw_w, dw_b, bhi, blo);
    gemm_mma_kernel<EPI_RES, 1, 1><<<dim3(E_ / 128, NTOK / 128), 256, GEMM_SMEM_B>>>(
        bhi, blo, whi + OFF_PW2_W, wlo + OFF_PW2_W, pw2_b, x2,
        x3, ahi, alo, NTOK, E_, E_);

    // 4) second FFN (FFN2 via split-K)
    gemm_mma_kernel<EPI_DSWISH, 0, 1><<<dim3(DFF_ / 128, NTOK / 128), 256, GEMM_SMEM_B>>>(
        ahi, alo, whi + OFF_FF_W1, wlo + OFF_FF_W1, ff_b1, nullptr,
        nullptr, bhi, blo, NTOK, DFF_, E_);
    gemm_mma_sk_kernel<<<dim3(E_ / 128, NTOK / 128, 2), 256, GEMM_SMEM_B>>>(
        bhi, blo, whi + OFF_FF_W2, wlo + OFF_FF_W2, ff, NTOK, E_, DFF_);
    combine_kernel<0, 1><<<(NTOK * E_ / 2 + 255) / 256, 256>>>(
        ff, ff_b2, x3, x1, nullptr, nullptr);

    // 5) BasicNorm -> output
    basic_norm_kernel<<<NTOK, 256>>>(x1, leps, (float*)d_out);
}

// round 14
// speedup vs baseline: 1.0610x; 1.0038x over previous
#include <cuda_runtime.h>
#include <cuda_bf16.h>
#include <math.h>
#include <stdint.h>

// ---------------- problem dims ----------------
#define T_    1024
#define B_    4
#define E_    512
#define H_    8
#define D_    64
#define DFF_  2048
#define NTOK  4096
#define PLEN  2047
#define KCONV 31

typedef unsigned long long u64;

// ---------------- scratch ----------------
__device__ float g_ff[NTOK * DFF_];
__device__ float g_x1[NTOK * E_];
__device__ float g_x2[NTOK * E_];
__device__ float g_x3[NTOK * E_];
__device__ float g_qkv[NTOK * 3 * E_];
__device__ float g_pproj[PLEN * E_];
__device__ float g_glu[NTOK * E_];
__device__ __nv_bfloat16 g_whi[7339520];
__device__ __nv_bfloat16 g_wlo[7339520];
__device__ __nv_bfloat16 g_ahi[NTOK * DFF_];
__device__ __nv_bfloat16 g_alo[NTOK * DFF_];
__device__ __nv_bfloat16 g_bhi[NTOK * DFF_];
__device__ __nv_bfloat16 g_blo[NTOK * DFF_];

// packed weight offsets (elements)
#define OFF_FFM_W1 0
#define OFF_FFM_W2 1048576
#define OFF_IN_W   2097152
#define OFF_WPOS   2883584
#define OFF_OUT_W  3145728
#define OFF_PW1_W  3407872
#define OFF_PW2_W  3932160
#define OFF_FF_W1  4194304
#define OFF_FF_W2  5242880
#define OFF_POSE   6291456

__device__ __forceinline__ float sigmoidf_(float x) { return 1.f / (1.f + __expf(-x)); }

// ---------------- packed f32x2 helpers ----------------
__device__ __forceinline__ u64 pack2_(float lo, float hi) {
    u64 r; asm("mov.b64 %0, {%1, %2};" : "=l"(r) : "f"(lo), "f"(hi)); return r;
}
__device__ __forceinline__ u64 pdup_(float x) {
    u64 r; asm("mov.b64 %0, {%1, %1};" : "=l"(r) : "f"(x)); return r;
}
__device__ __forceinline__ u64 ffma2_(u64 a, u64 b, u64 c) {
    u64 d; asm("fma.rn.f32x2 %0, %1, %2, %3;" : "=l"(d) : "l"(a), "l"(b), "l"(c)); return d;
}
__device__ __forceinline__ u64 mul2_(u64 a, u64 b) {
    u64 d; asm("mul.rn.f32x2 %0, %1, %2;" : "=l"(d) : "l"(a), "l"(b)); return d;
}
__device__ __forceinline__ u64 add2_(u64 a, u64 b) {
    u64 d; asm("add.rn.f32x2 %0, %1, %2;" : "=l"(d) : "l"(a), "l"(b)); return d;
}
__device__ __forceinline__ float2 unpack2_(u64 v) {
    float2 f; asm("mov.b64 {%0, %1}, %2;" : "=f"(f.x), "=f"(f.y) : "l"(v)); return f;
}
__device__ __forceinline__ uint32_t smem_u32_(const void* p) {
    return (uint32_t)__cvta_generic_to_shared(p);
}
__device__ __forceinline__ void cpasync16_(uint32_t dst, const void* src, int srcbytes) {
    asm volatile("cp.async.ca.shared.global [%0], [%1], 16, %2;"
                 :: "r"(dst), "l"(src), "r"(srcbytes));
}
__device__ __forceinline__ void split2_(float v0, float v1,
                                        __nv_bfloat16* hi, __nv_bfloat16* lo, size_t off) {
    __nv_bfloat16 h0 = __float2bfloat16(v0);
    __nv_bfloat16 h1 = __float2bfloat16(v1);
    __nv_bfloat162 hp; hp.x = h0; hp.y = h1;
    __nv_bfloat162 lp;
    lp.x = __float2bfloat16(v0 - __bfloat162float(h0));
    lp.y = __float2bfloat16(v1 - __bfloat162float(h1));
    *(__nv_bfloat162*)(hi + off) = hp;
    *(__nv_bfloat162*)(lo + off) = lp;
}

// ---------------- multi-segment hi/lo split ----------------
#define NSEG 11
struct SplitArgs {
    const float* src[NSEG];
    __nv_bfloat16* hi[NSEG];
    __nv_bfloat16* lo[NSEG];
    int n[NSEG];
};

__global__ void split_multi_kernel(SplitArgs a)
{
    int seg = blockIdx.y;
    int i = blockIdx.x * 256 + threadIdx.x;
    if (i >= a.n[seg]) return;
    float x = a.src[seg][i];
    __nv_bfloat16 h = __float2bfloat16(x);
    a.hi[seg][i] = h;
    a.lo[seg][i] = __float2bfloat16(x - __bfloat162float(h));
}

// ---------------- bf16 mma.sync NT GEMM: 128x128, fused 3-term, 2 CTAs/SM ----------------
enum { EPI_NONE = 0, EPI_DSWISH = 1, EPI_RES = 2 };
#define SSTRIDE 40
#define TILE_E  (128 * SSTRIDE)
#define STAGE_E (4 * TILE_E)
#define GEMM_SMEM_B (2 * STAGE_E * 2)    // 81920 bytes

template <int EPI, int WC, int WS>
__global__ void __launch_bounds__(256, 2)
gemm_mma_kernel(const __nv_bfloat16* __restrict__ Ahi, const __nv_bfloat16* __restrict__ Alo,
                const __nv_bfloat16* __restrict__ Bhi, const __nv_bfloat16* __restrict__ Blo,
                const float* __restrict__ bias, const float* __restrict__ res,
                float* __restrict__ C,
                __nv_bfloat16* __restrict__ Ohi, __nv_bfloat16* __restrict__ Olo,
                int M, int N, int K)
{
    extern __shared__ __nv_bfloat16 smem_g[];

    const int tid = threadIdx.x;
    const int wid = tid >> 5;
    const int lane = tid & 31;
    const int m0 = blockIdx.y * 128, n0 = blockIdx.x * 128;
    const int nk = K >> 5;

    const int mw = (wid & 1) * 64;
    const int nw = (wid >> 1) * 32;

    float acc[4][4][4];
#pragma unroll
    for (int a = 0; a < 4; a++)
#pragma unroll
        for (int b = 0; b < 4; b++)
#pragma unroll
            for (int c = 0; c < 4; c++) acc[a][b][c] = 0.f;

    const int r0 = tid >> 2,         col0 = (tid & 3) << 3;
    const int r1 = (tid + 256) >> 2, col1 = ((tid + 256) & 3) << 3;
    const uint32_t s_u = smem_u32_(smem_g);
    const uint32_t d0 = (uint32_t)(r0 * SSTRIDE + col0) * 2;
    const uint32_t d1 = (uint32_t)(r1 * SSTRIDE + col1) * 2;
    const int am0 = m0 + r0, am1 = m0 + r1;
    const int asz0 = am0 < M ? 16 : 0;
    const int asz1 = am1 < M ? 16 : 0;
    const size_t arow0 = (size_t)(am0 < M ? am0 : 0) * K;
    const size_t arow1 = (size_t)(am1 < M ? am1 : 0) * K;
    const size_t brow0 = (size_t)(n0 + r0) * K;
    const size_t brow1 = (size_t)(n0 + r1) * K;

    auto issue_loads = [&](int kt) {
        int kk0 = kt << 5;
        uint32_t so = (kt & 1) ? (uint32_t)STAGE_E * 2 : 0u;
        cpasync16_(s_u + so + d0, Ahi + arow0 + kk0 + col0, asz0);
        cpasync16_(s_u + so + d1, Ahi + arow1 + kk0 + col1, asz1);
        cpasync16_(s_u + so + TILE_E * 2 + d0, Alo + arow0 + kk0 + col0, asz0);
        cpasync16_(s_u + so + TILE_E * 2 + d1, Alo + arow1 + kk0 + col1, asz1);
        cpasync16_(s_u + so + 2 * TILE_E * 2 + d0, Bhi + brow0 + kk0 + col0, 16);
        cpasync16_(s_u + so + 2 * TILE_E * 2 + d1, Bhi + brow1 + kk0 + col1, 16);
        cpasync16_(s_u + so + 3 * TILE_E * 2 + d0, Blo + brow0 + kk0 + col0, 16);
        cpasync16_(s_u + so + 3 * TILE_E * 2 + d1, Blo + brow1 + kk0 + col1, 16);
    };

    issue_loads(0);
    asm volatile("cp.async.commit_group;" ::: "memory");

    const int lr8 = lane & 7;
    const int sel = lane >> 3;

#define MMA_(AH, BF)                                                            \
            _Pragma("unroll")                                                   \
            for (int mt = 0; mt < 4; mt++) {                                    \
                _Pragma("unroll")                                               \
                for (int nt = 0; nt < 4; nt++) {                                \
                    uint32_t b0 = BF[nt >> 1][(nt & 1) * 2 + 0];                \
                    uint32_t b1 = BF[nt >> 1][(nt & 1) * 2 + 1];                \
                    asm volatile(                                               \
                        "mma.sync.aligned.m16n8k16.row.col.f32.bf16.bf16.f32 "  \
                        "{%0,%1,%2,%3}, {%4,%5,%6,%7}, {%8,%9}, {%0,%1,%2,%3};" \
                        : "+f"(acc[mt][nt][0]), "+f"(acc[mt][nt][1]),           \
                          "+f"(acc[mt][nt][2]), "+f"(acc[mt][nt][3])            \
                        : "r"(AH[mt][0]), "r"(AH[mt][1]),                       \
                          "r"(AH[mt][2]), "r"(AH[mt][3]),                       \
                          "r"(b0), "r"(b1));                                    \
                }                                                               \
            }

    for (int kt = 0; kt < nk; kt++) {
        if (kt + 1 < nk) issue_loads(kt + 1);
        asm volatile("cp.async.commit_group;" ::: "memory");
        asm volatile("cp.async.wait_group 1;" ::: "memory");
        __syncthreads();

        const uint32_t base = s_u + ((kt & 1) ? (uint32_t)STAGE_E * 2 : 0u);
#pragma unroll
        for (int kk = 0; kk < 2; kk++) {
            uint32_t ahi[4][4];
#pragma unroll
            for (int mt = 0; mt < 4; mt++) {
                int row = mw + mt * 16 + lr8 + (sel & 1) * 8;
                int col = kk * 16 + (sel >> 1) * 8;
                uint32_t addr = base + (uint32_t)(row * SSTRIDE + col) * 2;
                asm volatile("ldmatrix.sync.aligned.m8n8.x4.shared.b16 {%0,%1,%2,%3}, [%4];"
                             : "=r"(ahi[mt][0]), "=r"(ahi[mt][1]), "=r"(ahi[mt][2]), "=r"(ahi[mt][3])
                             : "r"(addr));
            }
            uint32_t bfr[2][4];
#pragma unroll
            for (int np = 0; np < 2; np++) {
                int row = nw + np * 16 + lr8 + (sel >> 1) * 8;
                int col = kk * 16 + (sel & 1) * 8;
                uint32_t addr = base + 2 * TILE_E * 2 + (uint32_t)(row * SSTRIDE + col) * 2;
                asm volatile("ldmatrix.sync.aligned.m8n8.x4.shared.b16 {%0,%1,%2,%3}, [%4];"
                             : "=r"(bfr[np][0]), "=r"(bfr[np][1]), "=r"(bfr[np][2]), "=r"(bfr[np][3])
                             : "r"(addr));
            }
            MMA_(ahi, bfr)

            {
                uint32_t alo[4][4];
#pragma unroll
                for (int mt = 0; mt < 4; mt++) {
                    int row = mw + mt * 16 + lr8 + (sel & 1) * 8;
                    int col = kk * 16 + (sel >> 1) * 8;
                    uint32_t addr = base + TILE_E * 2 + (uint32_t)(row * SSTRIDE + col) * 2;
                    asm volatile("ldmatrix.sync.aligned.m8n8.x4.shared.b16 {%0,%1,%2,%3}, [%4];"
                                 : "=r"(alo[mt][0]), "=r"(alo[mt][1]), "=r"(alo[mt][2]), "=r"(alo[mt][3])
                                 : "r"(addr));
                }
                MMA_(alo, bfr)
            }

#pragma unroll
            for (int np = 0; np < 2; np++) {
                int row = nw + np * 16 + lr8 + (sel >> 1) * 8;
                int col = kk * 16 + (sel & 1) * 8;
                uint32_t addr = base + 3 * TILE_E * 2 + (uint32_t)(row * SSTRIDE + col) * 2;
                asm volatile("ldmatrix.sync.aligned.m8n8.x4.shared.b16 {%0,%1,%2,%3}, [%4];"
                             : "=r"(bfr[np][0]), "=r"(bfr[np][1]), "=r"(bfr[np][2]), "=r"(bfr[np][3])
                             : "r"(addr));
            }
            MMA_(ahi, bfr)
        }
        __syncthreads();
    }
#undef MMA_

    const int g = lane >> 2, t4 = lane & 3;
#pragma unroll
    for (int mt = 0; mt < 4; mt++) {
#pragma unroll
        for (int rr = 0; rr < 2; rr++) {
            int row = m0 + mw + mt * 16 + g + rr * 8;
            if (row >= M) continue;
#pragma unroll
            for (int nt = 0; nt < 4; nt++) {
                int col = n0 + nw + nt * 8 + t4 * 2;
                float v0 = acc[mt][nt][rr * 2 + 0];
                float v1 = acc[mt][nt][rr * 2 + 1];
                if (bias) { v0 += bias[col]; v1 += bias[col + 1]; }
                if (EPI == EPI_DSWISH) {
                    v0 = v0 * sigmoidf_(v0 - 1.f);
                    v1 = v1 * sigmoidf_(v1 - 1.f);
                }
                size_t off = (size_t)row * N + col;
                if (EPI == EPI_RES) {
                    float2 rv = *(const float2*)&res[off];
                    v0 += rv.x; v1 += rv.y;
                }
                if (WC) *(float2*)&C[off] = make_float2(v0, v1);
                if (WS) split2_(v0, v1, Ohi, Olo, off);
            }
        }
    }
}

// ---------------- split-K=2 variant: raw fp32 partials ----------------
__global__ void __launch_bounds__(256, 2)
gemm_mma_sk_kernel(const __nv_bfloat16* __restrict__ Ahi, const __nv_bfloat16* __restrict__ Alo,
                   const __nv_bfloat16* __restrict__ Bhi, const __nv_bfloat16* __restrict__ Blo,
                   float* __restrict__ Cpart, int M, int N, int K)
{
    extern __shared__ __nv_bfloat16 smem_g[];

    const int tid = threadIdx.x;
    const int wid = tid >> 5;
    const int lane = tid & 31;
    const int m0 = blockIdx.y * 128, n0 = blockIdx.x * 128;
    const int nk2 = (K >> 5) >> 1;
    const int ktb = blockIdx.z * nk2;

    const int mw = (wid & 1) * 64;
    const int nw = (wid >> 1) * 32;

    float acc[4][4][4];
#pragma unroll
    for (int a = 0; a < 4; a++)
#pragma unroll
        for (int b = 0; b < 4; b++)
#pragma unroll
            for (int c = 0; c < 4; c++) acc[a][b][c] = 0.f;

    const int r0 = tid >> 2,         col0 = (tid & 3) << 3;
    const int r1 = (tid + 256) >> 2, col1 = ((tid + 256) & 3) << 3;
    const uint32_t s_u = smem_u32_(smem_g);
    const uint32_t d0 = (uint32_t)(r0 * SSTRIDE + col0) * 2;
    const uint32_t d1 = (uint32_t)(r1 * SSTRIDE + col1) * 2;
    const size_t arow0 = (size_t)(m0 + r0) * K;
    const size_t arow1 = (size_t)(m0 + r1) * K;
    const size_t brow0 = (size_t)(n0 + r0) * K;
    const size_t brow1 = (size_t)(n0 + r1) * K;

    auto issue_loads = [&](int kt) {
        int kk0 = (ktb + kt) << 5;
        uint32_t so = (kt & 1) ? (uint32_t)STAGE_E * 2 : 0u;
        cpasync16_(s_u + so + d0, Ahi + arow0 + kk0 + col0, 16);
        cpasync16_(s_u + so + d1, Ahi + arow1 + kk0 + col1, 16);
        cpasync16_(s_u + so + TILE_E * 2 + d0, Alo + arow0 + kk0 + col0, 16);
        cpasync16_(s_u + so + TILE_E * 2 + d1, Alo + arow1 + kk0 + col1, 16);
        cpasync16_(s_u + so + 2 * TILE_E * 2 + d0, Bhi + brow0 + kk0 + col0, 16);
        cpasync16_(s_u + so + 2 * TILE_E * 2 + d1, Bhi + brow1 + kk0 + col1, 16);
        cpasync16_(s_u + so + 3 * TILE_E * 2 + d0, Blo + brow0 + kk0 + col0, 16);
        cpasync16_(s_u + so + 3 * TILE_E * 2 + d1, Blo + brow1 + kk0 + col1, 16);
    };

    issue_loads(0);
    asm volatile("cp.async.commit_group;" ::: "memory");

    const int lr8 = lane & 7;
    const int sel = lane >> 3;

#define MMA_(AH, BF)                                                            \
            _Pragma("unroll")                                                   \
            for (int mt = 0; mt < 4; mt++) {                                    \
                _Pragma("unroll")                                               \
                for (int nt = 0; nt < 4; nt++) {                                \
                    uint32_t b0 = BF[nt >> 1][(nt & 1) * 2 + 0];                \
                    uint32_t b1 = BF[nt >> 1][(nt & 1) * 2 + 1];                \
                    asm volatile(                                               \
                        "mma.sync.aligned.m16n8k16.row.col.f32.bf16.bf16.f32 "  \
                        "{%0,%1,%2,%3}, {%4,%5,%6,%7}, {%8,%9}, {%0,%1,%2,%3};" \
                        : "+f"(acc[mt][nt][0]), "+f"(acc[mt][nt][1]),           \
                          "+f"(acc[mt][nt][2]), "+f"(acc[mt][nt][3])            \
                        : "r"(AH[mt][0]), "r"(AH[mt][1]),                       \
                          "r"(AH[mt][2]), "r"(AH[mt][3]),                       \
                          "r"(b0), "r"(b1));                                    \
                }                                                               \
            }

    for (int kt = 0; kt < nk2; kt++) {
        if (kt + 1 < nk2) issue_loads(kt + 1);
        asm volatile("cp.async.commit_group;" ::: "memory");
        asm volatile("cp.async.wait_group 1;" ::: "memory");
        __syncthreads();

        const uint32_t base = s_u + ((kt & 1) ? (uint32_t)STAGE_E * 2 : 0u);
#pragma unroll
        for (int kk = 0; kk < 2; kk++) {
            uint32_t ahi[4][4];
#pragma unroll
            for (int mt = 0; mt < 4; mt++) {
                int row = mw + mt * 16 + lr8 + (sel & 1) * 8;
                int col = kk * 16 + (sel >> 1) * 8;
                uint32_t addr = base + (uint32_t)(row * SSTRIDE + col) * 2;
                asm volatile("ldmatrix.sync.aligned.m8n8.x4.shared.b16 {%0,%1,%2,%3}, [%4];"
                             : "=r"(ahi[mt][0]), "=r"(ahi[mt][1]), "=r"(ahi[mt][2]), "=r"(ahi[mt][3])
                             : "r"(addr));
            }
            uint32_t bfr[2][4];
#pragma unroll
            for (int np = 0; np < 2; np++) {
                int row = nw + np * 16 + lr8 + (sel >> 1) * 8;
                int col = kk * 16 + (sel & 1) * 8;
                uint32_t addr = base + 2 * TILE_E * 2 + (uint32_t)(row * SSTRIDE + col) * 2;
                asm volatile("ldmatrix.sync.aligned.m8n8.x4.shared.b16 {%0,%1,%2,%3}, [%4];"
                             : "=r"(bfr[np][0]), "=r"(bfr[np][1]), "=r"(bfr[np][2]), "=r"(bfr[np][3])
                             : "r"(addr));
            }
            MMA_(ahi, bfr)

            {
                uint32_t alo[4][4];
#pragma unroll
                for (int mt = 0; mt < 4; mt++) {
                    int row = mw + mt * 16 + lr8 + (sel & 1) * 8;
                    int col = kk * 16 + (sel >> 1) * 8;
                    uint32_t addr = base + TILE_E * 2 + (uint32_t)(row * SSTRIDE + col) * 2;
                    asm volatile("ldmatrix.sync.aligned.m8n8.x4.shared.b16 {%0,%1,%2,%3}, [%4];"
                                 : "=r"(alo[mt][0]), "=r"(alo[mt][1]), "=r"(alo[mt][2]), "=r"(alo[mt][3])
                                 : "r"(addr));
                }
                MMA_(alo, bfr)
            }

#pragma unroll
            for (int np = 0; np < 2; np++) {
                int row = nw + np * 16 + lr8 + (sel >> 1) * 8;
                int col = kk * 16 + (sel & 1) * 8;
                uint32_t addr = base + 3 * TILE_E * 2 + (uint32_t)(row * SSTRIDE + col) * 2;
                asm volatile("ldmatrix.sync.aligned.m8n8.x4.shared.b16 {%0,%1,%2,%3}, [%4];"
                             : "=r"(bfr[np][0]), "=r"(bfr[np][1]), "=r"(bfr[np][2]), "=r"(bfr[np][3])
                             : "r"(addr));
            }
            MMA_(ahi, bfr)
        }
        __syncthreads();
    }
#undef MMA_

    float* Cp = Cpart + (size_t)blockIdx.z * M * N;
    const int g = lane >> 2, t4 = lane & 3;
#pragma unroll
    for (int mt = 0; mt < 4; mt++) {
#pragma unroll
        for (int rr = 0; rr < 2; rr++) {
            int row = m0 + mw + mt * 16 + g + rr * 8;
#pragma unroll
            for (int nt = 0; nt < 4; nt++) {
                int col = n0 + nw + nt * 8 + t4 * 2;
                size_t off = (size_t)row * N + col;
                *(float2*)&Cp[off] = make_float2(acc[mt][nt][rr * 2 + 0],
                                                 acc[mt][nt][rr * 2 + 1]);
            }
        }
    }
}

// ---------------- split-K combine: C = part0 + part1 + bias + res ----------------
template <int WS, int WC>
__global__ void combine_kernel(const float* __restrict__ part, const float* __restrict__ bias,
                               const float* __restrict__ res, float* __restrict__ C,
                               __nv_bfloat16* __restrict__ Ohi, __nv_bfloat16* __restrict__ Olo)
{
    int i2 = blockIdx.x * 256 + threadIdx.x;
    if (i2 >= NTOK * E_ / 2) return;
    size_t off = (size_t)i2 * 2;
    int col = (int)(off & (E_ - 1));
    float2 p0 = *(const float2*)&part[off];
    float2 p1 = *(const float2*)&part[off + (size_t)NTOK * E_];
    float2 rv = *(const float2*)&res[off];
    float v0 = p0.x + p1.x + bias[col] + rv.x;
    float v1 = p0.y + p1.y + bias[col + 1] + rv.y;
    if (WC) *(float2*)&C[off] = make_float2(v0, v1);
    if (WS) split2_(v0, v1, Ohi, Olo, off);
}

// ---------------- fused attention (vectorized Ps window, 2 CTAs/SM) ----------------
#define ATTN_SMEM ((64 * 68 + 64 + 64 * 68 + 64 * 128 + 64 * 68 + 64 * 68) * 4)

__global__ void __launch_bounds__(256, 2)
attn_fused_kernel(const float* __restrict__ qkv,
                  const float* __restrict__ pproj,
                  const float* __restrict__ u,
                  const float* __restrict__ v,
                  __nv_bfloat16* __restrict__ chi,
                  __nv_bfloat16* __restrict__ clo)
{
    extern __shared__ float sm[];
    float* Qu  = sm;                    // [d][i]  stride 68
    float* duv = Qu + 64 * 68;          // [64]
    float* Kt  = duv + 64;              // [d][j]  stride 68
    float* Ps  = Kt + 64 * 68;          // [d][mm] stride 128
    float* Vs  = Ps + 64 * 128;         // [k][d]  stride 68
    float* Es  = Vs + 64 * 68;          // [i][k]  stride 68

    const int bh = blockIdx.y;
    const int b = bh >> 3, h = bh & 7;
    const int i0 = blockIdx.x * 64;
    const int tid = threadIdx.x;
    const float scale = 0.125f;

    for (int idx = tid; idx < 64 * 64; idx += 256) {
        int li = idx >> 6, d = idx & 63;
        float q = qkv[(size_t)((i0 + li) * B_ + b) * (3 * E_) + h * 64 + d] * scale;
        Qu[d * 68 + li] = q + u[h * 64 + d];
    }
    if (tid < 64) duv[tid] = v[h * 64 + tid] - u[h * 64 + tid];

    const int tm = (tid >> 4) << 2;
    const int tn = (tid & 15) << 2;
    const int base = 63 - tm + tn;      // base-3 is a multiple of 4

    float mrow[4], lrow[4];
#pragma unroll
    for (int i = 0; i < 4; i++) { mrow[i] = -1e30f; lrow[i] = 0.f; }
    u64 outacc[4][2];
#pragma unroll
    for (int i = 0; i < 4; i++) { outacc[i][0] = 0ull; outacc[i][1] = 0ull; }

    for (int j0 = 0; j0 < T_; j0 += 64) {
        __syncthreads();
        for (int idx = tid; idx < 64 * 64; idx += 256) {
            int li = idx >> 6, d = idx & 63;
            size_t rb = (size_t)((j0 + li) * B_ + b) * (3 * E_) + h * 64 + d;
            Kt[d * 68 + li] = qkv[rb + E_];
            Vs[li * 68 + d] = qkv[rb + 2 * E_];
        }
        const int m_min = 960 - i0 + j0;
        for (int idx = tid; idx < 64 * 127; idx += 256) {
            int d = idx / 127, mm = idx % 127;
            Ps[d * 128 + mm] = pproj[(size_t)(m_min + mm) * E_ + h * 64 + d];
        }
        __syncthreads();

        u64 acc2[4][2];
#pragma unroll
        for (int i = 0; i < 4; i++) { acc2[i][0] = 0ull; acc2[i][1] = 0ull; }

#pragma unroll 4
        for (int d = 0; d < 64; d++) {
            u64 duv2 = pdup_(duv[d]);
            float4 qu4 = *(const float4*)&Qu[d * 68 + tm];
            ulonglong2 ktp = *(const ulonglong2*)&Kt[d * 68 + tn];
            u64 ad[4], cd[4];
            ad[0] = pdup_(qu4.x); ad[1] = pdup_(qu4.y);
            ad[2] = pdup_(qu4.z); ad[3] = pdup_(qu4.w);
#pragma unroll
            for (int ii = 0; ii < 4; ii++) cd[ii] = add2_(ad[ii], duv2);
            float4 pa = *(const float4*)&Ps[d * 128 + base - 3];
            float4 pb = *(const float4*)&Ps[d * 128 + base + 1];
            float p7[7] = {pa.x, pa.y, pa.z, pa.w, pb.x, pb.y, pb.z};
            u64 pp[6];
#pragma unroll
            for (int t = 0; t < 6; t++) pp[t] = pack2_(p7[t], p7[t + 1]);
#pragma unroll
            for (int ii = 0; ii < 4; ii++) {
                acc2[ii][0] = ffma2_(ad[ii], ktp.x, acc2[ii][0]);
                acc2[ii][1] = ffma2_(ad[ii], ktp.y, acc2[ii][1]);
                acc2[ii][0] = ffma2_(cd[ii], pp[3 - ii], acc2[ii][0]);
                acc2[ii][1] = ffma2_(cd[ii], pp[5 - ii], acc2[ii][1]);
            }
        }

#pragma unroll
        for (int ii = 0; ii < 4; ii++) {
            float2 t0 = unpack2_(acc2[ii][0]);
            float2 t1 = unpack2_(acc2[ii][1]);
            float s0 = t0.x, s1 = t0.y, s2 = t1.x, s3 = t1.y;
            float mx = fmaxf(fmaxf(s0, s1), fmaxf(s2, s3));
#pragma unroll
            for (int o = 1; o < 16; o <<= 1)
                mx = fmaxf(mx, __shfl_xor_sync(0xffffffffu, mx, o));
            float mnew = fmaxf(mrow[ii], mx);
            float alpha = __expf(mrow[ii] - mnew);
            mrow[ii] = mnew;
            s0 = __expf(s0 - mnew); s1 = __expf(s1 - mnew);
            s2 = __expf(s2 - mnew); s3 = __expf(s3 - mnew);
            float rs = s0 + s1 + s2 + s3;
#pragma unroll
            for (int o = 1; o < 16; o <<= 1)
                rs += __shfl_xor_sync(0xffffffffu, rs, o);
            lrow[ii] = lrow[ii] * alpha + rs;
            u64 al = pdup_(alpha);
            outacc[ii][0] = mul2_(outacc[ii][0], al);
            outacc[ii][1] = mul2_(outacc[ii][1], al);
            *(float4*)&Es[(tm + ii) * 68 + tn] = make_float4(s0, s1, s2, s3);
        }
        __syncthreads();

        // AV: unroll kk by 4, float4 Es loads
#pragma unroll 2
        for (int kk = 0; kk < 64; kk += 4) {
            float e[4][4];
#pragma unroll
            for (int ii = 0; ii < 4; ii++)
                *(float4*)&e[ii][0] = *(const float4*)&Es[(tm + ii) * 68 + kk];
#pragma unroll
            for (int j = 0; j < 4; j++) {
                ulonglong2 bq = *(const ulonglong2*)&Vs[(kk + j) * 68 + tn];
#pragma unroll
                for (int ii = 0; ii < 4; ii++) {
                    u64 a = pdup_(e[ii][j]);
                    outacc[ii][0] = ffma2_(a, bq.x, outacc[ii][0]);
                    outacc[ii][1] = ffma2_(a, bq.y, outacc[ii][1]);
                }
            }
        }
    }

#pragma unroll
    for (int ii = 0; ii < 4; ii++) {
        float inv = 1.f / lrow[ii];
        float2 t0 = unpack2_(outacc[ii][0]);
        float2 t1 = unpack2_(outacc[ii][1]);
        size_t off = (size_t)((i0 + tm + ii) * B_ + b) * E_ + h * 64 + tn;
        split2_(t0.x * inv, t0.y * inv, chi, clo, off);
        split2_(t1.x * inv, t1.y * inv, chi, clo, off + 2);
    }
}

// ---------------- GLU ----------------
__global__ void glu_kernel(const float* __restrict__ y, float* __restrict__ out)
{
    int idx = blockIdx.x * 256 + threadIdx.x;
    if (idx >= NTOK * E_) return;
    int r = idx >> 9, c = idx & 511;
    float a = y[(size_t)r * 1024 + c];
    float g = y[(size_t)r * 1024 + 512 + c];
    out[idx] = a * sigmoidf_(g);
}

// ---------------- depthwise conv + DoubleSwish -> split bf16 ----------------
__global__ void dwconv_kernel(const float* __restrict__ x, const float* __restrict__ w,
                              const float* __restrict__ bias,
                              __nv_bfloat16* __restrict__ ohi, __nv_bfloat16* __restrict__ olo)
{
    int idx = blockIdx.x * 256 + threadIdx.x;
    if (idx >= NTOK * E_) return;
    int c = idx & 511;
    int tb = idx >> 9;
    int t = tb >> 2, b = tb & 3;
    float acc = bias[c];
#pragma unroll
    for (int k = 0; k < KCONV; k++) {
        int tt = t + k - 15;
        if (tt >= 0 && tt < T_)
            acc += x[(size_t)(tt * B_ + b) * E_ + c] * w[c * KCONV + k];
    }
    float vv = acc * sigmoidf_(acc - 1.f);
    __nv_bfloat16 h = __float2bfloat16(vv);
    ohi[idx] = h;
    olo[idx] = __float2bfloat16(vv - __bfloat162float(h));
}

// ---------------- BasicNorm ----------------
__global__ void basic_norm_kernel(const float* __restrict__ x, const float* __restrict__ leps,
                                  float* __restrict__ out)
{
    __shared__ float red[8];
    const int tid = threadIdx.x;
    const float* p = x + (size_t)blockIdx.x * E_;
    float v0 = p[tid], v1 = p[tid + 256];
    float ss = v0 * v0 + v1 * v1;
#pragma unroll
    for (int o = 16; o > 0; o >>= 1) ss += __shfl_xor_sync(0xffffffffu, ss, o);
    if ((tid & 31) == 0) red[tid >> 5] = ss;
    __syncthreads();
    float tot = red[0];
#pragma unroll
    for (int i = 1; i < 8; i++) tot += red[i];
    float r = rsqrtf(tot * (1.f / (float)E_) + __expf(leps[0]));
    out[(size_t)blockIdx.x * E_ + tid]       = v0 * r;
    out[(size_t)blockIdx.x * E_ + tid + 256] = v1 * r;
}

// ---------------- launch ----------------
extern "C" void kernel_launch(void* const* d_in, const int* in_sizes, int n_in,
                              void* d_out, int out_size)
{
    const float* src      = (const float*)d_in[0];
    const float* pos_emb  = (const float*)d_in[1];
    const float* in_w     = (const float*)d_in[2];
    const float* in_b     = (const float*)d_in[3];
    const float* out_w    = (const float*)d_in[4];
    const float* out_b    = (const float*)d_in[5];
    const float* wpos     = (const float*)d_in[6];
    const float* u        = (const float*)d_in[7];
    const float* v        = (const float*)d_in[8];
    const float* ffm_w1   = (const float*)d_in[9];
    const float* ffm_b1   = (const float*)d_in[10];
    const float* ffm_w2   = (const float*)d_in[11];
    const float* ffm_b2   = (const float*)d_in[12];
    const float* ff_w1    = (const float*)d_in[13];
    const float* ff_b1    = (const float*)d_in[14];
    const float* ff_w2    = (const float*)d_in[15];
    const float* ff_b2    = (const float*)d_in[16];
    const float* pw1_w    = (const float*)d_in[17];
    const float* pw1_b    = (const float*)d_in[18];
    const float* dw_w     = (const float*)d_in[19];
    const float* dw_b     = (const float*)d_in[20];
    const float* pw2_w    = (const float*)d_in[21];
    const float* pw2_b    = (const float*)d_in[22];
    const float* leps     = (const float*)d_in[23];

    float *ff, *x1, *x2, *x3, *qkv, *pp, *glu;
    __nv_bfloat16 *whi, *wlo, *ahi, *alo, *bhi, *blo;
    cudaGetSymbolAddress((void**)&ff,  g_ff);
    cudaGetSymbolAddress((void**)&x1,  g_x1);
    cudaGetSymbolAddress((void**)&x2,  g_x2);
    cudaGetSymbolAddress((void**)&x3,  g_x3);
    cudaGetSymbolAddress((void**)&qkv, g_qkv);
    cudaGetSymbolAddress((void**)&pp,  g_pproj);
    cudaGetSymbolAddress((void**)&glu, g_glu);
    cudaGetSymbolAddress((void**)&whi, g_whi);
    cudaGetSymbolAddress((void**)&wlo, g_wlo);
    cudaGetSymbolAddress((void**)&ahi, g_ahi);
    cudaGetSymbolAddress((void**)&alo, g_alo);
    cudaGetSymbolAddress((void**)&bhi, g_bhi);
    cudaGetSymbolAddress((void**)&blo, g_blo);

    cudaFuncSetAttribute(attn_fused_kernel, cudaFuncAttributeMaxDynamicSharedMemorySize,
                         ATTN_SMEM);
#define SET_GSMEM(EPI, WC, WS) \
    cudaFuncSetAttribute((gemm_mma_kernel<EPI, WC, WS>), \
                         cudaFuncAttributeMaxDynamicSharedMemorySize, GEMM_SMEM_B)
    SET_GSMEM(EPI_DSWISH, 0, 1);
    SET_GSMEM(EPI_NONE, 1, 0);
#undef SET_GSMEM
    cudaFuncSetAttribute(gemm_mma_sk_kernel, cudaFuncAttributeMaxDynamicSharedMemorySize,
                         GEMM_SMEM_B);

    // launch 0: all splits in one kernel
    SplitArgs sa;
    sa.src[0] = ffm_w1;  sa.hi[0] = whi + OFF_FFM_W1; sa.lo[0] = wlo + OFF_FFM_W1; sa.n[0] = DFF_ * E_;
    sa.src[1] = ffm_w2;  sa.hi[1] = whi + OFF_FFM_W2; sa.lo[1] = wlo + OFF_FFM_W2; sa.n[1] = E_ * DFF_;
    sa.src[2] = in_w;    sa.hi[2] = whi + OFF_IN_W;   sa.lo[2] = wlo + OFF_IN_W;   sa.n[2] = 3 * E_ * E_;
    sa.src[3] = wpos;    sa.hi[3] = whi + OFF_WPOS;   sa.lo[3] = wlo + OFF_WPOS;   sa.n[3] = E_ * E_;
    sa.src[4] = out_w;   sa.hi[4] = whi + OFF_OUT_W;  sa.lo[4] = wlo + OFF_OUT_W;  sa.n[4] = E_ * E_;
    sa.src[5] = pw1_w;   sa.hi[5] = whi + OFF_PW1_W;  sa.lo[5] = wlo + OFF_PW1_W;  sa.n[5] = 2 * E_ * E_;
    sa.src[6] = pw2_w;   sa.hi[6] = whi + OFF_PW2_W;  sa.lo[6] = wlo + OFF_PW2_W;  sa.n[6] = E_ * E_;
    sa.src[7] = ff_w1;   sa.hi[7] = whi + OFF_FF_W1;  sa.lo[7] = wlo + OFF_FF_W1;  sa.n[7] = DFF_ * E_;
    sa.src[8] = ff_w2;   sa.hi[8] = whi + OFF_FF_W2;  sa.lo[8] = wlo + OFF_FF_W2;  sa.n[8] = E_ * DFF_;
    sa.src[9] = pos_emb; sa.hi[9] = whi + OFF_POSE;   sa.lo[9] = wlo + OFF_POSE;   sa.n[9] = PLEN * E_;
    sa.src[10] = src;    sa.hi[10] = ahi;             sa.lo[10] = alo;             sa.n[10] = NTOK * E_;
    split_multi_kernel<<<dim3(8192, NSEG), 256>>>(sa);

    // 1) macaron FFN (FFN2 via split-K)
    gemm_mma_kernel<EPI_DSWISH, 0, 1><<<dim3(DFF_ / 128, NTOK / 128), 256, GEMM_SMEM_B>>>(
        ahi, alo, whi + OFF_FFM_W1, wlo + OFF_FFM_W1, ffm_b1, nullptr,
        nullptr, bhi, blo, NTOK, DFF_, E_);
    gemm_mma_sk_kernel<<<dim3(E_ / 128, NTOK / 128, 2), 256, GEMM_SMEM_B>>>(
        bhi, blo, whi + OFF_FFM_W2, wlo + OFF_FFM_W2, ff, NTOK, E_, DFF_);
    combine_kernel<1, 1><<<(NTOK * E_ / 2 + 255) / 256, 256>>>(
        ff, ffm_b2, src, x1, ahi, alo);

    // 2) attention
    gemm_mma_kernel<EPI_NONE, 1, 0><<<dim3((3 * E_) / 128, NTOK / 128), 256, GEMM_SMEM_B>>>(
        ahi, alo, whi + OFF_IN_W, wlo + OFF_IN_W, in_b, nullptr,
        qkv, nullptr, nullptr, NTOK, 3 * E_, E_);
    gemm_mma_kernel<EPI_NONE, 1, 0><<<dim3(E_ / 128, (PLEN + 127) / 128), 256, GEMM_SMEM_B>>>(
        whi + OFF_POSE, wlo + OFF_POSE, whi + OFF_WPOS, wlo + OFF_WPOS, nullptr, nullptr,
        pp, nullptr, nullptr, PLEN, E_, E_);
    attn_fused_kernel<<<dim3(T_ / 64, B_ * H_), 256, ATTN_SMEM>>>(qkv, pp, u, v, bhi, blo);
    gemm_mma_sk_kernel<<<dim3(E_ / 128, NTOK / 128, 2), 256, GEMM_SMEM_B>>>(
        bhi, blo, whi + OFF_OUT_W, wlo + OFF_OUT_W, ff, NTOK, E_, E_);
    combine_kernel<1, 1><<<(NTOK * E_ / 2 + 255) / 256, 256>>>(
        ff, out_b, x1, x2, ahi, alo);

    // 3) conv module
    gemm_mma_kernel<EPI_NONE, 1, 0><<<dim3((2 * E_) / 128, NTOK / 128), 256, GEMM_SMEM_B>>>(
        ahi, alo, whi + OFF_PW1_W, wlo + OFF_PW1_W, pw1_b, nullptr,
        ff, nullptr, nullptr, NTOK, 2 * E_, E_);
    glu_kernel<<<(NTOK * E_) / 256, 256>>>(ff, glu);
    dwconv_kernel<<<(NTOK * E_) / 256, 256>>>(glu, dw_w, dw_b, bhi, blo);
    gemm_mma_sk_kernel<<<dim3(E_ / 128, NTOK / 128, 2), 256, GEMM_SMEM_B>>>(
        bhi, blo, whi + OFF_PW2_W, wlo + OFF_PW2_W, ff, NTOK, E_, E_);
    combine_kernel<1, 1><<<(NTOK * E_ / 2 + 255) / 256, 256>>>(
        ff, pw2_b, x2, x3, ahi, alo);

    // 4) second FFN (FFN2 via split-K)
    gemm_mma_kernel<EPI_DSWISH, 0, 1><<<dim3(DFF_ / 128, NTOK / 128), 256, GEMM_SMEM_B>>>(
        ahi, alo, whi + OFF_FF_W1, wlo + OFF_FF_W1, ff_b1, nullptr,
        nullptr, bhi, blo, NTOK, DFF_, E_);
    gemm_mma_sk_kernel<<<dim3(E_ / 128, NTOK / 128, 2), 256, GEMM_SMEM_B>>>(
        bhi, blo, whi + OFF_FF_W2, wlo + OFF_FF_W2, ff, NTOK, E_, DFF_);
    combine_kernel<0, 1><<<(NTOK * E_ / 2 + 255) / 256, 256>>>(
        ff, ff_b2, x3, x1, nullptr, nullptr);

    // 5) BasicNorm -> output
    basic_norm_kernel<<<NTOK, 256>>>(x1, leps, (float*)d_out);
}

// round 15
// speedup vs baseline: 1.0814x; 1.0192x over previous
#include <cuda_runtime.h>
#include <cuda_bf16.h>
#include <math.h>
#include <stdint.h>

// ---------------- problem dims ----------------
#define T_    1024
#define B_    4
#define E_    512
#define H_    8
#define D_    64
#define DFF_  2048
#define NTOK  4096
#define PLEN  2047
#define KCONV 31

typedef unsigned long long u64;

// ---------------- scratch ----------------
__device__ float g_ff[NTOK * DFF_];
__device__ float g_x1[NTOK * E_];
__device__ float g_x2[NTOK * E_];
__device__ float g_x3[NTOK * E_];
__device__ float g_qkv[NTOK * 3 * E_];
__device__ float g_pproj[PLEN * E_];
__device__ float g_glu[NTOK * E_];
__device__ __nv_bfloat16 g_whi[7339520];
__device__ __nv_bfloat16 g_wlo[7339520];
__device__ __nv_bfloat16 g_ahi[NTOK * DFF_];
__device__ __nv_bfloat16 g_alo[NTOK * DFF_];
__device__ __nv_bfloat16 g_bhi[NTOK * DFF_];
__device__ __nv_bfloat16 g_blo[NTOK * DFF_];

// packed weight offsets (elements)
#define OFF_FFM_W1 0
#define OFF_FFM_W2 1048576
#define OFF_IN_W   2097152
#define OFF_WPOS   2883584
#define OFF_OUT_W  3145728
#define OFF_PW1_W  3407872
#define OFF_PW2_W  3932160
#define OFF_FF_W1  4194304
#define OFF_FF_W2  5242880
#define OFF_POSE   6291456

__device__ __forceinline__ float sigmoidf_(float x) { return 1.f / (1.f + __expf(-x)); }

// ---------------- packed f32x2 helpers ----------------
__device__ __forceinline__ u64 pack2_(float lo, float hi) {
    u64 r; asm("mov.b64 %0, {%1, %2};" : "=l"(r) : "f"(lo), "f"(hi)); return r;
}
__device__ __forceinline__ u64 pdup_(float x) {
    u64 r; asm("mov.b64 %0, {%1, %1};" : "=l"(r) : "f"(x)); return r;
}
__device__ __forceinline__ u64 ffma2_(u64 a, u64 b, u64 c) {
    u64 d; asm("fma.rn.f32x2 %0, %1, %2, %3;" : "=l"(d) : "l"(a), "l"(b), "l"(c)); return d;
}
__device__ __forceinline__ u64 mul2_(u64 a, u64 b) {
    u64 d; asm("mul.rn.f32x2 %0, %1, %2;" : "=l"(d) : "l"(a), "l"(b)); return d;
}
__device__ __forceinline__ u64 add2_(u64 a, u64 b) {
    u64 d; asm("add.rn.f32x2 %0, %1, %2;" : "=l"(d) : "l"(a), "l"(b)); return d;
}
__device__ __forceinline__ float2 unpack2_(u64 v) {
    float2 f; asm("mov.b64 {%0, %1}, %2;" : "=f"(f.x), "=f"(f.y) : "l"(v)); return f;
}
__device__ __forceinline__ uint32_t smem_u32_(const void* p) {
    return (uint32_t)__cvta_generic_to_shared(p);
}
__device__ __forceinline__ void cpasync16_(uint32_t dst, const void* src, int srcbytes) {
    asm volatile("cp.async.ca.shared.global [%0], [%1], 16, %2;"
                 :: "r"(dst), "l"(src), "r"(srcbytes));
}
__device__ __forceinline__ void split2_(float v0, float v1,
                                        __nv_bfloat16* hi, __nv_bfloat16* lo, size_t off) {
    __nv_bfloat16 h0 = __float2bfloat16(v0);
    __nv_bfloat16 h1 = __float2bfloat16(v1);
    __nv_bfloat162 hp; hp.x = h0; hp.y = h1;
    __nv_bfloat162 lp;
    lp.x = __float2bfloat16(v0 - __bfloat162float(h0));
    lp.y = __float2bfloat16(v1 - __bfloat162float(h1));
    *(__nv_bfloat162*)(hi + off) = hp;
    *(__nv_bfloat162*)(lo + off) = lp;
}

// ---------------- multi-segment hi/lo split ----------------
#define NSEG 11
struct SplitArgs {
    const float* src[NSEG];
    __nv_bfloat16* hi[NSEG];
    __nv_bfloat16* lo[NSEG];
    int n[NSEG];
};

__global__ void split_multi_kernel(SplitArgs a)
{
    int seg = blockIdx.y;
    int i = blockIdx.x * 256 + threadIdx.x;
    if (i >= a.n[seg]) return;
    float x = a.src[seg][i];
    __nv_bfloat16 h = __float2bfloat16(x);
    a.hi[seg][i] = h;
    a.lo[seg][i] = __float2bfloat16(x - __bfloat162float(h));
}

// ---------------- bf16 mma.sync NT GEMM: 128x128, fused 3-term, 2 CTAs/SM ----------------
enum { EPI_NONE = 0, EPI_DSWISH = 1, EPI_RES = 2 };
#define SSTRIDE 40
#define TILE_E  (128 * SSTRIDE)
#define STAGE_E (4 * TILE_E)
#define GEMM_SMEM_B (2 * STAGE_E * 2)    // 81920 bytes

// shared mainloop body (expects locals: smem ptr s_u, pointers, dims)
#define GEMM_BODY(M_, N_, K_, Ahi_, Alo_, Bhi_, Blo_)                                       \
    const int nk = (K_) >> 5;                                                               \
    const int mw = (wid & 1) * 64;                                                          \
    const int nw = (wid >> 1) * 32;                                                         \
    float acc[4][4][4];                                                                     \
    _Pragma("unroll") for (int a = 0; a < 4; a++)                                           \
        _Pragma("unroll") for (int b = 0; b < 4; b++)                                       \
            _Pragma("unroll") for (int c = 0; c < 4; c++) acc[a][b][c] = 0.f;               \
    const int r0 = tid >> 2,         col0 = (tid & 3) << 3;                                 \
    const int r1 = (tid + 256) >> 2, col1 = ((tid + 256) & 3) << 3;                         \
    const uint32_t d0 = (uint32_t)(r0 * SSTRIDE + col0) * 2;                                \
    const uint32_t d1 = (uint32_t)(r1 * SSTRIDE + col1) * 2;                                \
    const int am0 = m0 + r0, am1 = m0 + r1;                                                 \
    const int asz0 = am0 < (M_) ? 16 : 0;                                                   \
    const int asz1 = am1 < (M_) ? 16 : 0;                                                   \
    const size_t arow0 = (size_t)(am0 < (M_) ? am0 : 0) * (K_);                             \
    const size_t arow1 = (size_t)(am1 < (M_) ? am1 : 0) * (K_);                             \
    const size_t brow0 = (size_t)(n0 + r0) * (K_);                                          \
    const size_t brow1 = (size_t)(n0 + r1) * (K_);                                          \
    auto issue_loads = [&](int kt) {                                                        \
        int kk0 = kt << 5;                                                                  \
        uint32_t so = (kt & 1) ? (uint32_t)STAGE_E * 2 : 0u;                                \
        cpasync16_(s_u + so + d0, (Ahi_) + arow0 + kk0 + col0, asz0);                       \
        cpasync16_(s_u + so + d1, (Ahi_) + arow1 + kk0 + col1, asz1);                       \
        cpasync16_(s_u + so + TILE_E * 2 + d0, (Alo_) + arow0 + kk0 + col0, asz0);          \
        cpasync16_(s_u + so + TILE_E * 2 + d1, (Alo_) + arow1 + kk0 + col1, asz1);          \
        cpasync16_(s_u + so + 2 * TILE_E * 2 + d0, (Bhi_) + brow0 + kk0 + col0, 16);        \
        cpasync16_(s_u + so + 2 * TILE_E * 2 + d1, (Bhi_) + brow1 + kk0 + col1, 16);        \
        cpasync16_(s_u + so + 3 * TILE_E * 2 + d0, (Blo_) + brow0 + kk0 + col0, 16);        \
        cpasync16_(s_u + so + 3 * TILE_E * 2 + d1, (Blo_) + brow1 + kk0 + col1, 16);        \
    };                                                                                      \
    issue_loads(0);                                                                         \
    asm volatile("cp.async.commit_group;" ::: "memory");                                    \
    const int lr8 = lane & 7;                                                               \
    const int sel = lane >> 3;                                                              \
    for (int kt = 0; kt < nk; kt++) {                                                       \
        if (kt + 1 < nk) issue_loads(kt + 1);                                               \
        asm volatile("cp.async.commit_group;" ::: "memory");                                \
        asm volatile("cp.async.wait_group 1;" ::: "memory");                                \
        __syncthreads();                                                                    \
        const uint32_t base = s_u + ((kt & 1) ? (uint32_t)STAGE_E * 2 : 0u);                \
        _Pragma("unroll")                                                                   \
        for (int kk = 0; kk < 2; kk++) {                                                    \
            uint32_t ahi[4][4];                                                             \
            _Pragma("unroll")                                                               \
            for (int mt = 0; mt < 4; mt++) {                                                \
                int row = mw + mt * 16 + lr8 + (sel & 1) * 8;                               \
                int col = kk * 16 + (sel >> 1) * 8;                                         \
                uint32_t addr = base + (uint32_t)(row * SSTRIDE + col) * 2;                 \
                asm volatile("ldmatrix.sync.aligned.m8n8.x4.shared.b16 {%0,%1,%2,%3}, [%4];"\
                             : "=r"(ahi[mt][0]), "=r"(ahi[mt][1]),                          \
                               "=r"(ahi[mt][2]), "=r"(ahi[mt][3]) : "r"(addr));             \
            }                                                                               \
            uint32_t bfr[2][4];                                                             \
            _Pragma("unroll")                                                               \
            for (int np = 0; np < 2; np++) {                                                \
                int row = nw + np * 16 + lr8 + (sel >> 1) * 8;                              \
                int col = kk * 16 + (sel & 1) * 8;                                          \
                uint32_t addr = base + 2 * TILE_E * 2 + (uint32_t)(row * SSTRIDE + col) * 2;\
                asm volatile("ldmatrix.sync.aligned.m8n8.x4.shared.b16 {%0,%1,%2,%3}, [%4];"\
                             : "=r"(bfr[np][0]), "=r"(bfr[np][1]),                          \
                               "=r"(bfr[np][2]), "=r"(bfr[np][3]) : "r"(addr));             \
            }                                                                               \
            MMA_(ahi, bfr)                                                                  \
            {                                                                               \
                uint32_t alo[4][4];                                                         \
                _Pragma("unroll")                                                           \
                for (int mt = 0; mt < 4; mt++) {                                            \
                    int row = mw + mt * 16 + lr8 + (sel & 1) * 8;                           \
                    int col = kk * 16 + (sel >> 1) * 8;                                     \
                    uint32_t addr = base + TILE_E * 2 + (uint32_t)(row * SSTRIDE + col) * 2;\
                    asm volatile("ldmatrix.sync.aligned.m8n8.x4.shared.b16 {%0,%1,%2,%3}, [%4];"\
                                 : "=r"(alo[mt][0]), "=r"(alo[mt][1]),                      \
                                   "=r"(alo[mt][2]), "=r"(alo[mt][3]) : "r"(addr));         \
                }                                                                           \
                MMA_(alo, bfr)                                                              \
            }                                                                               \
            _Pragma("unroll")                                                               \
            for (int np = 0; np < 2; np++) {                                                \
                int row = nw + np * 16 + lr8 + (sel >> 1) * 8;                              \
                int col = kk * 16 + (sel & 1) * 8;                                          \
                uint32_t addr = base + 3 * TILE_E * 2 +                                     \
                                (uint32_t)(row * SSTRIDE + col) * 2;                        \
                asm volatile("ldmatrix.sync.aligned.m8n8.x4.shared.b16 {%0,%1,%2,%3}, [%4];"\
                             : "=r"(bfr[np][0]), "=r"(bfr[np][1]),                          \
                               "=r"(bfr[np][2]), "=r"(bfr[np][3]) : "r"(addr));             \
            }                                                                               \
            MMA_(ahi, bfr)                                                                  \
        }                                                                                   \
        __syncthreads();                                                                    \
    }

#define MMA_(AH, BF)                                                            \
            _Pragma("unroll")                                                   \
            for (int mt = 0; mt < 4; mt++) {                                    \
                _Pragma("unroll")                                               \
                for (int nt = 0; nt < 4; nt++) {                                \
                    uint32_t b0 = BF[nt >> 1][(nt & 1) * 2 + 0];                \
                    uint32_t b1 = BF[nt >> 1][(nt & 1) * 2 + 1];                \
                    asm volatile(                                               \
                        "mma.sync.aligned.m16n8k16.row.col.f32.bf16.bf16.f32 "  \
                        "{%0,%1,%2,%3}, {%4,%5,%6,%7}, {%8,%9}, {%0,%1,%2,%3};" \
                        : "+f"(acc[mt][nt][0]), "+f"(acc[mt][nt][1]),           \
                          "+f"(acc[mt][nt][2]), "+f"(acc[mt][nt][3])            \
                        : "r"(AH[mt][0]), "r"(AH[mt][1]),                       \
                          "r"(AH[mt][2]), "r"(AH[mt][3]),                       \
                          "r"(b0), "r"(b1));                                    \
                }                                                               \
            }

template <int EPI, int WC, int WS>
__global__ void __launch_bounds__(256, 2)
gemm_mma_kernel(const __nv_bfloat16* __restrict__ Ahi, const __nv_bfloat16* __restrict__ Alo,
                const __nv_bfloat16* __restrict__ Bhi, const __nv_bfloat16* __restrict__ Blo,
                const float* __restrict__ bias, const float* __restrict__ res,
                float* __restrict__ C,
                __nv_bfloat16* __restrict__ Ohi, __nv_bfloat16* __restrict__ Olo,
                int M, int N, int K)
{
    extern __shared__ __nv_bfloat16 smem_g[];
    const int tid = threadIdx.x;
    const int wid = tid >> 5;
    const int lane = tid & 31;
    const int m0 = blockIdx.y * 128, n0 = blockIdx.x * 128;
    const uint32_t s_u = smem_u32_(smem_g);

    GEMM_BODY(M, N, K, Ahi, Alo, Bhi, Blo)

    const int g = lane >> 2, t4 = lane & 3;
#pragma unroll
    for (int mt = 0; mt < 4; mt++) {
#pragma unroll
        for (int rr = 0; rr < 2; rr++) {
            int row = m0 + mw + mt * 16 + g + rr * 8;
            if (row >= M) continue;
#pragma unroll
            for (int nt = 0; nt < 4; nt++) {
                int col = n0 + nw + nt * 8 + t4 * 2;
                float v0 = acc[mt][nt][rr * 2 + 0];
                float v1 = acc[mt][nt][rr * 2 + 1];
                if (bias) { v0 += bias[col]; v1 += bias[col + 1]; }
                if (EPI == EPI_DSWISH) {
                    v0 = v0 * sigmoidf_(v0 - 1.f);
                    v1 = v1 * sigmoidf_(v1 - 1.f);
                }
                size_t off = (size_t)row * N + col;
                if (EPI == EPI_RES) {
                    float2 rv = *(const float2*)&res[off];
                    v0 += rv.x; v1 += rv.y;
                }
                if (WC) *(float2*)&C[off] = make_float2(v0, v1);
                if (WS) split2_(v0, v1, Ohi, Olo, off);
            }
        }
    }
}

// ---------------- dual GEMM: blockIdx.x < 12 -> QKV (N=1536), else -> pos (N=512) ----------
__global__ void __launch_bounds__(256, 2)
gemm_dual_kernel(const __nv_bfloat16* __restrict__ A1hi, const __nv_bfloat16* __restrict__ A1lo,
                 const __nv_bfloat16* __restrict__ B1hi, const __nv_bfloat16* __restrict__ B1lo,
                 const float* __restrict__ bias1, float* __restrict__ C1,
                 const __nv_bfloat16* __restrict__ A2hi, const __nv_bfloat16* __restrict__ A2lo,
                 const __nv_bfloat16* __restrict__ B2hi, const __nv_bfloat16* __restrict__ B2lo,
                 float* __restrict__ C2)
{
    extern __shared__ __nv_bfloat16 smem_g[];
    const int tid = threadIdx.x;
    const int wid = tid >> 5;
    const int lane = tid & 31;
    const bool second = blockIdx.x >= 12;
    if (second && blockIdx.y >= 16) return;          // pos M=2047 -> 16 y-tiles

    const int m0 = blockIdx.y * 128;
    const int n0 = (second ? (blockIdx.x - 12) : blockIdx.x) * 128;
    const int M = second ? PLEN : NTOK;
    const int N = second ? E_ : 3 * E_;
    const int K = E_;
    const __nv_bfloat16* Ahi = second ? A2hi : A1hi;
    const __nv_bfloat16* Alo = second ? A2lo : A1lo;
    const __nv_bfloat16* Bhi = second ? B2hi : B1hi;
    const __nv_bfloat16* Blo = second ? B2lo : B1lo;
    const float* bias = second ? nullptr : bias1;
    float* C = second ? C2 : C1;
    const uint32_t s_u = smem_u32_(smem_g);

    GEMM_BODY(M, N, K, Ahi, Alo, Bhi, Blo)

    const int g = lane >> 2, t4 = lane & 3;
#pragma unroll
    for (int mt = 0; mt < 4; mt++) {
#pragma unroll
        for (int rr = 0; rr < 2; rr++) {
            int row = m0 + mw + mt * 16 + g + rr * 8;
            if (row >= M) continue;
#pragma unroll
            for (int nt = 0; nt < 4; nt++) {
                int col = n0 + nw + nt * 8 + t4 * 2;
                float v0 = acc[mt][nt][rr * 2 + 0];
                float v1 = acc[mt][nt][rr * 2 + 1];
                if (bias) { v0 += bias[col]; v1 += bias[col + 1]; }
                size_t off = (size_t)row * N + col;
                *(float2*)&C[off] = make_float2(v0, v1);
            }
        }
    }
}

// ---------------- split-K=2 variant: raw fp32 partials ----------------
__global__ void __launch_bounds__(256, 2)
gemm_mma_sk_kernel(const __nv_bfloat16* __restrict__ Ahi, const __nv_bfloat16* __restrict__ Alo,
                   const __nv_bfloat16* __restrict__ Bhi, const __nv_bfloat16* __restrict__ Blo,
                   float* __restrict__ Cpart, int M, int N, int K)
{
    extern __shared__ __nv_bfloat16 smem_g[];
    const int tid = threadIdx.x;
    const int wid = tid >> 5;
    const int lane = tid & 31;
    const int m0 = blockIdx.y * 128, n0 = blockIdx.x * 128;
    const int nk2 = (K >> 5) >> 1;
    const int Koff = blockIdx.z * (K >> 1);
    const uint32_t s_u = smem_u32_(smem_g);
    const __nv_bfloat16* Ahi2 = Ahi + Koff;
    const __nv_bfloat16* Alo2 = Alo + Koff;
    const __nv_bfloat16* Bhi2 = Bhi + Koff;
    const __nv_bfloat16* Blo2 = Blo + Koff;

    // GEMM_BODY with K loop bounded at nk2 and row strides of full K
    const int mw = (wid & 1) * 64;
    const int nw = (wid >> 1) * 32;
    float acc[4][4][4];
#pragma unroll
    for (int a = 0; a < 4; a++)
#pragma unroll
        for (int b = 0; b < 4; b++)
#pragma unroll
            for (int c = 0; c < 4; c++) acc[a][b][c] = 0.f;
    const int r0 = tid >> 2,         col0 = (tid & 3) << 3;
    const int r1 = (tid + 256) >> 2, col1 = ((tid + 256) & 3) << 3;
    const uint32_t d0 = (uint32_t)(r0 * SSTRIDE + col0) * 2;
    const uint32_t d1 = (uint32_t)(r1 * SSTRIDE + col1) * 2;
    const size_t arow0 = (size_t)(m0 + r0) * K;
    const size_t arow1 = (size_t)(m0 + r1) * K;
    const size_t brow0 = (size_t)(n0 + r0) * K;
    const size_t brow1 = (size_t)(n0 + r1) * K;
    auto issue_loads = [&](int kt) {
        int kk0 = kt << 5;
        uint32_t so = (kt & 1) ? (uint32_t)STAGE_E * 2 : 0u;
        cpasync16_(s_u + so + d0, Ahi2 + arow0 + kk0 + col0, 16);
        cpasync16_(s_u + so + d1, Ahi2 + arow1 + kk0 + col1, 16);
        cpasync16_(s_u + so + TILE_E * 2 + d0, Alo2 + arow0 + kk0 + col0, 16);
        cpasync16_(s_u + so + TILE_E * 2 + d1, Alo2 + arow1 + kk0 + col1, 16);
        cpasync16_(s_u + so + 2 * TILE_E * 2 + d0, Bhi2 + brow0 + kk0 + col0, 16);
        cpasync16_(s_u + so + 2 * TILE_E * 2 + d1, Bhi2 + brow1 + kk0 + col1, 16);
        cpasync16_(s_u + so + 3 * TILE_E * 2 + d0, Blo2 + brow0 + kk0 + col0, 16);
        cpasync16_(s_u + so + 3 * TILE_E * 2 + d1, Blo2 + brow1 + kk0 + col1, 16);
    };
    issue_loads(0);
    asm volatile("cp.async.commit_group;" ::: "memory");
    const int lr8 = lane & 7;
    const int sel = lane >> 3;
    for (int kt = 0; kt < nk2; kt++) {
        if (kt + 1 < nk2) issue_loads(kt + 1);
        asm volatile("cp.async.commit_group;" ::: "memory");
        asm volatile("cp.async.wait_group 1;" ::: "memory");
        __syncthreads();
        const uint32_t base = s_u + ((kt & 1) ? (uint32_t)STAGE_E * 2 : 0u);
#pragma unroll
        for (int kk = 0; kk < 2; kk++) {
            uint32_t ahi[4][4];
#pragma unroll
            for (int mt = 0; mt < 4; mt++) {
                int row = mw + mt * 16 + lr8 + (sel & 1) * 8;
                int col = kk * 16 + (sel >> 1) * 8;
                uint32_t addr = base + (uint32_t)(row * SSTRIDE + col) * 2;
                asm volatile("ldmatrix.sync.aligned.m8n8.x4.shared.b16 {%0,%1,%2,%3}, [%4];"
                             : "=r"(ahi[mt][0]), "=r"(ahi[mt][1]), "=r"(ahi[mt][2]), "=r"(ahi[mt][3])
                             : "r"(addr));
            }
            uint32_t bfr[2][4];
#pragma unroll
            for (int np = 0; np < 2; np++) {
                int row = nw + np * 16 + lr8 + (sel >> 1) * 8;
                int col = kk * 16 + (sel & 1) * 8;
                uint32_t addr = base + 2 * TILE_E * 2 + (uint32_t)(row * SSTRIDE + col) * 2;
                asm volatile("ldmatrix.sync.aligned.m8n8.x4.shared.b16 {%0,%1,%2,%3}, [%4];"
                             : "=r"(bfr[np][0]), "=r"(bfr[np][1]), "=r"(bfr[np][2]), "=r"(bfr[np][3])
                             : "r"(addr));
            }
            MMA_(ahi, bfr)
            {
                uint32_t alo[4][4];
#pragma unroll
                for (int mt = 0; mt < 4; mt++) {
                    int row = mw + mt * 16 + lr8 + (sel & 1) * 8;
                    int col = kk * 16 + (sel >> 1) * 8;
                    uint32_t addr = base + TILE_E * 2 + (uint32_t)(row * SSTRIDE + col) * 2;
                    asm volatile("ldmatrix.sync.aligned.m8n8.x4.shared.b16 {%0,%1,%2,%3}, [%4];"
                                 : "=r"(alo[mt][0]), "=r"(alo[mt][1]), "=r"(alo[mt][2]), "=r"(alo[mt][3])
                                 : "r"(addr));
                }
                MMA_(alo, bfr)
            }
#pragma unroll
            for (int np = 0; np < 2; np++) {
                int row = nw + np * 16 + lr8 + (sel >> 1) * 8;
                int col = kk * 16 + (sel & 1) * 8;
                uint32_t addr = base + 3 * TILE_E * 2 + (uint32_t)(row * SSTRIDE + col) * 2;
                asm volatile("ldmatrix.sync.aligned.m8n8.x4.shared.b16 {%0,%1,%2,%3}, [%4];"
                             : "=r"(bfr[np][0]), "=r"(bfr[np][1]), "=r"(bfr[np][2]), "=r"(bfr[np][3])
                             : "r"(addr));
            }
            MMA_(ahi, bfr)
        }
        __syncthreads();
    }

    float* Cp = Cpart + (size_t)blockIdx.z * M * N;
    const int g = lane >> 2, t4 = lane & 3;
#pragma unroll
    for (int mt = 0; mt < 4; mt++) {
#pragma unroll
        for (int rr = 0; rr < 2; rr++) {
            int row = m0 + mw + mt * 16 + g + rr * 8;
#pragma unroll
            for (int nt = 0; nt < 4; nt++) {
                int col = n0 + nw + nt * 8 + t4 * 2;
                size_t off = (size_t)row * N + col;
                *(float2*)&Cp[off] = make_float2(acc[mt][nt][rr * 2 + 0],
                                                 acc[mt][nt][rr * 2 + 1]);
            }
        }
    }
}

// ---------------- split-K combine ----------------
template <int WS, int WC>
__global__ void combine_kernel(const float* __restrict__ part, const float* __restrict__ bias,
                               const float* __restrict__ res, float* __restrict__ C,
                               __nv_bfloat16* __restrict__ Ohi, __nv_bfloat16* __restrict__ Olo)
{
    int i2 = blockIdx.x * 256 + threadIdx.x;
    if (i2 >= NTOK * E_ / 2) return;
    size_t off = (size_t)i2 * 2;
    int col = (int)(off & (E_ - 1));
    float2 p0 = *(const float2*)&part[off];
    float2 p1 = *(const float2*)&part[off + (size_t)NTOK * E_];
    float2 rv = *(const float2*)&res[off];
    float v0 = p0.x + p1.x + bias[col] + rv.x;
    float v1 = p0.y + p1.y + bias[col + 1] + rv.y;
    if (WC) *(float2*)&C[off] = make_float2(v0, v1);
    if (WS) split2_(v0, v1, Ohi, Olo, off);
}

// ---------------- fused attention ----------------
#define ATTN_SMEM ((64 * 68 + 64 + 64 * 68 + 64 * 128 + 64 * 68 + 64 * 68) * 4)

__global__ void __launch_bounds__(256, 2)
attn_fused_kernel(const float* __restrict__ qkv,
                  const float* __restrict__ pproj,
                  const float* __restrict__ u,
                  const float* __restrict__ v,
                  __nv_bfloat16* __restrict__ chi,
                  __nv_bfloat16* __restrict__ clo)
{
    extern __shared__ float sm[];
    float* Qu  = sm;
    float* duv = Qu + 64 * 68;
    float* Kt  = duv + 64;
    float* Ps  = Kt + 64 * 68;
    float* Vs  = Ps + 64 * 128;
    float* Es  = Vs + 64 * 68;

    const int bh = blockIdx.y;
    const int b = bh >> 3, h = bh & 7;
    const int i0 = blockIdx.x * 64;
    const int tid = threadIdx.x;
    const float scale = 0.125f;

    for (int idx = tid; idx < 64 * 64; idx += 256) {
        int li = idx >> 6, d = idx & 63;
        float q = qkv[(size_t)((i0 + li) * B_ + b) * (3 * E_) + h * 64 + d] * scale;
        Qu[d * 68 + li] = q + u[h * 64 + d];
    }
    if (tid < 64) duv[tid] = v[h * 64 + tid] - u[h * 64 + tid];

    const int tm = (tid >> 4) << 2;
    const int tn = (tid & 15) << 2;
    const int base = 63 - tm + tn;

    float mrow[4], lrow[4];
#pragma unroll
    for (int i = 0; i < 4; i++) { mrow[i] = -1e30f; lrow[i] = 0.f; }
    u64 outacc[4][2];
#pragma unroll
    for (int i = 0; i < 4; i++) { outacc[i][0] = 0ull; outacc[i][1] = 0ull; }

    for (int j0 = 0; j0 < T_; j0 += 64) {
        __syncthreads();
        for (int idx = tid; idx < 64 * 64; idx += 256) {
            int li = idx >> 6, d = idx & 63;
            size_t rb = (size_t)((j0 + li) * B_ + b) * (3 * E_) + h * 64 + d;
            Kt[d * 68 + li] = qkv[rb + E_];
            Vs[li * 68 + d] = qkv[rb + 2 * E_];
        }
        const int m_min = 960 - i0 + j0;
        for (int idx = tid; idx < 64 * 127; idx += 256) {
            int d = idx / 127, mm = idx % 127;
            Ps[d * 128 + mm] = pproj[(size_t)(m_min + mm) * E_ + h * 64 + d];
        }
        __syncthreads();

        u64 acc2[4][2];
#pragma unroll
        for (int i = 0; i < 4; i++) { acc2[i][0] = 0ull; acc2[i][1] = 0ull; }

#pragma unroll 4
        for (int d = 0; d < 64; d++) {
            u64 duv2 = pdup_(duv[d]);
            float4 qu4 = *(const float4*)&Qu[d * 68 + tm];
            ulonglong2 ktp = *(const ulonglong2*)&Kt[d * 68 + tn];
            u64 ad[4], cd[4];
            ad[0] = pdup_(qu4.x); ad[1] = pdup_(qu4.y);
            ad[2] = pdup_(qu4.z); ad[3] = pdup_(qu4.w);
#pragma unroll
            for (int ii = 0; ii < 4; ii++) cd[ii] = add2_(ad[ii], duv2);
            float4 pa = *(const float4*)&Ps[d * 128 + base - 3];
            float4 pb = *(const float4*)&Ps[d * 128 + base + 1];
            float p7[7] = {pa.x, pa.y, pa.z, pa.w, pb.x, pb.y, pb.z};
            u64 pp[6];
#pragma unroll
            for (int t = 0; t < 6; t++) pp[t] = pack2_(p7[t], p7[t + 1]);
#pragma unroll
            for (int ii = 0; ii < 4; ii++) {
                acc2[ii][0] = ffma2_(ad[ii], ktp.x, acc2[ii][0]);
                acc2[ii][1] = ffma2_(ad[ii], ktp.y, acc2[ii][1]);
                acc2[ii][0] = ffma2_(cd[ii], pp[3 - ii], acc2[ii][0]);
                acc2[ii][1] = ffma2_(cd[ii], pp[5 - ii], acc2[ii][1]);
            }
        }

#pragma unroll
        for (int ii = 0; ii < 4; ii++) {
            float2 t0 = unpack2_(acc2[ii][0]);
            float2 t1 = unpack2_(acc2[ii][1]);
            float s0 = t0.x, s1 = t0.y, s2 = t1.x, s3 = t1.y;
            float mx = fmaxf(fmaxf(s0, s1), fmaxf(s2, s3));
#pragma unroll
            for (int o = 1; o < 16; o <<= 1)
                mx = fmaxf(mx, __shfl_xor_sync(0xffffffffu, mx, o));
            float mnew = fmaxf(mrow[ii], mx);
            float alpha = __expf(mrow[ii] - mnew);
            mrow[ii] = mnew;
            s0 = __expf(s0 - mnew); s1 = __expf(s1 - mnew);
            s2 = __expf(s2 - mnew); s3 = __expf(s3 - mnew);
            float rs = s0 + s1 + s2 + s3;
#pragma unroll
            for (int o = 1; o < 16; o <<= 1)
                rs += __shfl_xor_sync(0xffffffffu, rs, o);
            lrow[ii] = lrow[ii] * alpha + rs;
            u64 al = pdup_(alpha);
            outacc[ii][0] = mul2_(outacc[ii][0], al);
            outacc[ii][1] = mul2_(outacc[ii][1], al);
            *(float4*)&Es[(tm + ii) * 68 + tn] = make_float4(s0, s1, s2, s3);
        }
        __syncthreads();

#pragma unroll 2
        for (int kk = 0; kk < 64; kk += 4) {
            float e[4][4];
#pragma unroll
            for (int ii = 0; ii < 4; ii++)
                *(float4*)&e[ii][0] = *(const float4*)&Es[(tm + ii) * 68 + kk];
#pragma unroll
            for (int j = 0; j < 4; j++) {
                ulonglong2 bq = *(const ulonglong2*)&Vs[(kk + j) * 68 + tn];
#pragma unroll
                for (int ii = 0; ii < 4; ii++) {
                    u64 a = pdup_(e[ii][j]);
                    outacc[ii][0] = ffma2_(a, bq.x, outacc[ii][0]);
                    outacc[ii][1] = ffma2_(a, bq.y, outacc[ii][1]);
                }
            }
        }
    }

#pragma unroll
    for (int ii = 0; ii < 4; ii++) {
        float inv = 1.f / lrow[ii];
        float2 t0 = unpack2_(outacc[ii][0]);
        float2 t1 = unpack2_(outacc[ii][1]);
        size_t off = (size_t)((i0 + tm + ii) * B_ + b) * E_ + h * 64 + tn;
        split2_(t0.x * inv, t0.y * inv, chi, clo, off);
        split2_(t1.x * inv, t1.y * inv, chi, clo, off + 2);
    }
}

// ---------------- GLU ----------------
__global__ void glu_kernel(const float* __restrict__ y, float* __restrict__ out)
{
    int idx = blockIdx.x * 256 + threadIdx.x;
    if (idx >= NTOK * E_) return;
    int r = idx >> 9, c = idx & 511;
    float a = y[(size_t)r * 1024 + c];
    float g = y[(size_t)r * 1024 + 512 + c];
    out[idx] = a * sigmoidf_(g);
}

// ---------------- depthwise conv + DoubleSwish -> split bf16 ----------------
__global__ void dwconv_kernel(const float* __restrict__ x, const float* __restrict__ w,
                              const float* __restrict__ bias,
                              __nv_bfloat16* __restrict__ ohi, __nv_bfloat16* __restrict__ olo)
{
    int idx = blockIdx.x * 256 + threadIdx.x;
    if (idx >= NTOK * E_) return;
    int c = idx & 511;
    int tb = idx >> 9;
    int t = tb >> 2, b = tb & 3;
    float acc = bias[c];
#pragma unroll
    for (int k = 0; k < KCONV; k++) {
        int tt = t + k - 15;
        if (tt >= 0 && tt < T_)
            acc += x[(size_t)(tt * B_ + b) * E_ + c] * w[c * KCONV + k];
    }
    float vv = acc * sigmoidf_(acc - 1.f);
    __nv_bfloat16 h = __float2bfloat16(vv);
    ohi[idx] = h;
    olo[idx] = __float2bfloat16(vv - __bfloat162float(h));
}

// ---------------- BasicNorm ----------------
__global__ void basic_norm_kernel(const float* __restrict__ x, const float* __restrict__ leps,
                                  float* __restrict__ out)
{
    __shared__ float red[8];
    const int tid = threadIdx.x;
    const float* p = x + (size_t)blockIdx.x * E_;
    float v0 = p[tid], v1 = p[tid + 256];
    float ss = v0 * v0 + v1 * v1;
#pragma unroll
    for (int o = 16; o > 0; o >>= 1) ss += __shfl_xor_sync(0xffffffffu, ss, o);
    if ((tid & 31) == 0) red[tid >> 5] = ss;
    __syncthreads();
    float tot = red[0];
#pragma unroll
    for (int i = 1; i < 8; i++) tot += red[i];
    float r = rsqrtf(tot * (1.f / (float)E_) + __expf(leps[0]));
    out[(size_t)blockIdx.x * E_ + tid]       = v0 * r;
    out[(size_t)blockIdx.x * E_ + tid + 256] = v1 * r;
}

// ---------------- launch ----------------
extern "C" void kernel_launch(void* const* d_in, const int* in_sizes, int n_in,
                              void* d_out, int out_size)
{
    const float* src      = (const float*)d_in[0];
    const float* pos_emb  = (const float*)d_in[1];
    const float* in_w     = (const float*)d_in[2];
    const float* in_b     = (const float*)d_in[3];
    const float* out_w    = (const float*)d_in[4];
    const float* out_b    = (const float*)d_in[5];
    const float* wpos     = (const float*)d_in[6];
    const float* u        = (const float*)d_in[7];
    const float* v        = (const float*)d_in[8];
    const float* ffm_w1   = (const float*)d_in[9];
    const float* ffm_b1   = (const float*)d_in[10];
    const float* ffm_w2   = (const float*)d_in[11];
    const float* ffm_b2   = (const float*)d_in[12];
    const float* ff_w1    = (const float*)d_in[13];
    const float* ff_b1    = (const float*)d_in[14];
    const float* ff_w2    = (const float*)d_in[15];
    const float* ff_b2    = (const float*)d_in[16];
    const float* pw1_w    = (const float*)d_in[17];
    const float* pw1_b    = (const float*)d_in[18];
    const float* dw_w     = (const float*)d_in[19];
    const float* dw_b     = (const float*)d_in[20];
    const float* pw2_w    = (const float*)d_in[21];
    const float* pw2_b    = (const float*)d_in[22];
    const float* leps     = (const float*)d_in[23];

    float *ff, *x1, *x2, *x3, *qkv, *pp, *glu;
    __nv_bfloat16 *whi, *wlo, *ahi, *alo, *bhi, *blo;
    cudaGetSymbolAddress((void**)&ff,  g_ff);
    cudaGetSymbolAddress((void**)&x1,  g_x1);
    cudaGetSymbolAddress((void**)&x2,  g_x2);
    cudaGetSymbolAddress((void**)&x3,  g_x3);
    cudaGetSymbolAddress((void**)&qkv, g_qkv);
    cudaGetSymbolAddress((void**)&pp,  g_pproj);
    cudaGetSymbolAddress((void**)&glu, g_glu);
    cudaGetSymbolAddress((void**)&whi, g_whi);
    cudaGetSymbolAddress((void**)&wlo, g_wlo);
    cudaGetSymbolAddress((void**)&ahi, g_ahi);
    cudaGetSymbolAddress((void**)&alo, g_alo);
    cudaGetSymbolAddress((void**)&bhi, g_bhi);
    cudaGetSymbolAddress((void**)&blo, g_blo);

    cudaFuncSetAttribute(attn_fused_kernel, cudaFuncAttributeMaxDynamicSharedMemorySize,
                         ATTN_SMEM);
#define SET_GSMEM(EPI, WC, WS) \
    cudaFuncSetAttribute((gemm_mma_kernel<EPI, WC, WS>), \
                         cudaFuncAttributeMaxDynamicSharedMemorySize, GEMM_SMEM_B)
    SET_GSMEM(EPI_DSWISH, 0, 1);
    SET_GSMEM(EPI_NONE, 1, 0);
#undef SET_GSMEM
    cudaFuncSetAttribute(gemm_mma_sk_kernel, cudaFuncAttributeMaxDynamicSharedMemorySize,
                         GEMM_SMEM_B);
    cudaFuncSetAttribute(gemm_dual_kernel, cudaFuncAttributeMaxDynamicSharedMemorySize,
                         GEMM_SMEM_B);

    // launch 0: all splits in one kernel
    SplitArgs sa;
    sa.src[0] = ffm_w1;  sa.hi[0] = whi + OFF_FFM_W1; sa.lo[0] = wlo + OFF_FFM_W1; sa.n[0] = DFF_ * E_;
    sa.src[1] = ffm_w2;  sa.hi[1] = whi + OFF_FFM_W2; sa.lo[1] = wlo + OFF_FFM_W2; sa.n[1] = E_ * DFF_;
    sa.src[2] = in_w;    sa.hi[2] = whi + OFF_IN_W;   sa.lo[2] = wlo + OFF_IN_W;   sa.n[2] = 3 * E_ * E_;
    sa.src[3] = wpos;    sa.hi[3] = whi + OFF_WPOS;   sa.lo[3] = wlo + OFF_WPOS;   sa.n[3] = E_ * E_;
    sa.src[4] = out_w;   sa.hi[4] = whi + OFF_OUT_W;  sa.lo[4] = wlo + OFF_OUT_W;  sa.n[4] = E_ * E_;
    sa.src[5] = pw1_w;   sa.hi[5] = whi + OFF_PW1_W;  sa.lo[5] = wlo + OFF_PW1_W;  sa.n[5] = 2 * E_ * E_;
    sa.src[6] = pw2_w;   sa.hi[6] = whi + OFF_PW2_W;  sa.lo[6] = wlo + OFF_PW2_W;  sa.n[6] = E_ * E_;
    sa.src[7] = ff_w1;   sa.hi[7] = whi + OFF_FF_W1;  sa.lo[7] = wlo + OFF_FF_W1;  sa.n[7] = DFF_ * E_;
    sa.src[8] = ff_w2;   sa.hi[8] = whi + OFF_FF_W2;  sa.lo[8] = wlo + OFF_FF_W2;  sa.n[8] = E_ * DFF_;
    sa.src[9] = pos_emb; sa.hi[9] = whi + OFF_POSE;   sa.lo[9] = wlo + OFF_POSE;   sa.n[9] = PLEN * E_;
    sa.src[10] = src;    sa.hi[10] = ahi;             sa.lo[10] = alo;             sa.n[10] = NTOK * E_;
    split_multi_kernel<<<dim3(8192, NSEG), 256>>>(sa);

    // 1) macaron FFN (FFN2 via split-K)
    gemm_mma_kernel<EPI_DSWISH, 0, 1><<<dim3(DFF_ / 128, NTOK / 128), 256, GEMM_SMEM_B>>>(
        ahi, alo, whi + OFF_FFM_W1, wlo + OFF_FFM_W1, ffm_b1, nullptr,
        nullptr, bhi, blo, NTOK, DFF_, E_);
    gemm_mma_sk_kernel<<<dim3(E_ / 128, NTOK / 128, 2), 256, GEMM_SMEM_B>>>(
        bhi, blo, whi + OFF_FFM_W2, wlo + OFF_FFM_W2, ff, NTOK, E_, DFF_);
    combine_kernel<1, 1><<<(NTOK * E_ / 2 + 255) / 256, 256>>>(
        ff, ffm_b2, src, x1, ahi, alo);

    // 2) attention: fused qkv + pos GEMM (launch 4), then attn (launch 5)
    gemm_dual_kernel<<<dim3(16, 32), 256, GEMM_SMEM_B>>>(
        ahi, alo, whi + OFF_IN_W, wlo + OFF_IN_W, in_b, qkv,
        whi + OFF_POSE, wlo + OFF_POSE, whi + OFF_WPOS, wlo + OFF_WPOS, pp);
    attn_fused_kernel<<<dim3(T_ / 64, B_ * H_), 256, ATTN_SMEM>>>(qkv, pp, u, v, bhi, blo);
    gemm_mma_sk_kernel<<<dim3(E_ / 128, NTOK / 128, 2), 256, GEMM_SMEM_B>>>(
        bhi, blo, whi + OFF_OUT_W, wlo + OFF_OUT_W, ff, NTOK, E_, E_);
    combine_kernel<1, 1><<<(NTOK * E_ / 2 + 255) / 256, 256>>>(
        ff, out_b, x1, x2, ahi, alo);

    // 3) conv module
    gemm_mma_kernel<EPI_NONE, 1, 0><<<dim3((2 * E_) / 128, NTOK / 128), 256, GEMM_SMEM_B>>>(
        ahi, alo, whi + OFF_PW1_W, wlo + OFF_PW1_W, pw1_b, nullptr,
        ff, nullptr, nullptr, NTOK, 2 * E_, E_);
    glu_kernel<<<(NTOK * E_) / 256, 256>>>(ff, glu);
    dwconv_kernel<<<(NTOK * E_) / 256, 256>>>(glu, dw_w, dw_b, bhi, blo);
    gemm_mma_sk_kernel<<<dim3(E_ / 128, NTOK / 128, 2), 256, GEMM_SMEM_B>>>(
        bhi, blo, whi + OFF_PW2_W, wlo + OFF_PW2_W, ff, NTOK, E_, E_);
    combine_kernel<1, 1><<<(NTOK * E_ / 2 + 255) / 256, 256>>>(
        ff, pw2_b, x2, x3, ahi, alo);

    // 4) second FFN (FFN2 via split-K)
    gemm_mma_kernel<EPI_DSWISH, 0, 1><<<dim3(DFF_ / 128, NTOK / 128), 256, GEMM_SMEM_B>>>(
        ahi, alo, whi + OFF_FF_W1, wlo + OFF_FF_W1, ff_b1, nullptr,
        nullptr, bhi, blo, NTOK, DFF_, E_);
    gemm_mma_sk_kernel<<<dim3(E_ / 128, NTOK / 128, 2), 256, GEMM_SMEM_B>>>(
        bhi, blo, whi + OFF_FF_W2, wlo + OFF_FF_W2, ff, NTOK, E_, DFF_);
    combine_kernel<0, 1><<<(NTOK * E_ / 2 + 255) / 256, 256>>>(
        ff, ff_b2, x3, x1, nullptr, nullptr);

    // 5) BasicNorm -> output
    basic_norm_kernel<<<NTOK, 256>>>(x1, leps, (float*)d_out);
}